// round 14
// baseline (speedup 1.0000x reference)
#include <cuda_runtime.h>
#include <cuda_fp16.h>
#include <math.h>
#include <stdint.h>

#define Bb 32
#define Nn 512
#define Ee 2048
#define Dd 128
#define NSTEP 3
#define MROWS (Bb*Nn)          // 16384

// ---------------- scratch (device globals: allocation-free) ----------------
__device__ float g_G0   [MROWS*Dd];
__device__ float g_split[2*MROWS*Dd];   // split-K partials for G0
__device__ float g_rAp  [2*MROWS];
__device__ float g_prop [MROWS*Dd];
__device__ float g_rp   [MROWS*Dd];
__device__ float g_zbuf [MROWS*Dd];
__device__ float g_outn [MROWS*Dd];
__device__ float g_rA   [MROWS];
__device__ float g_WrzTs[3*256*256];    // per-step folded [N=256][K=256]
__device__ float g_TTs  [3*Dd*256];     // per-step folded [N=128][K=256]
__device__ float g_betarz[3*256];
__device__ float g_betah [3*Dd];
__device__ float g_brz  [256];
__device__ float g_attW1T[Dd*Dd];
__device__ float g_outWT [Dd*Dd];
__device__ float g_W2   [Dd*Dd];
__device__ float g_W3   [Dd*Dd];
__device__ float g_W3T  [Dd*Dd];
__device__ float g_c    [3*Dd];
__device__ float g_att  [Bb*Nn];
__device__ float g_part [Bb*20*Dd];

// ---------------- fp16 mma helpers ------------------------------------------
__device__ __forceinline__ uint32_t packh2(float x, float y) {
    __half2 h = __floats2half2_rn(x, y);
    return *(uint32_t*)&h;
}
__device__ __forceinline__ void mma_f16(float* c, const uint32_t* a, const uint32_t* b) {
    asm volatile("mma.sync.aligned.m16n8k16.row.col.f32.f16.f16.f32 "
                 "{%0,%1,%2,%3},{%4,%5,%6,%7},{%8,%9},{%0,%1,%2,%3};"
                 : "+f"(c[0]), "+f"(c[1]), "+f"(c[2]), "+f"(c[3])
                 : "r"(a[0]), "r"(a[1]), "r"(a[2]), "r"(a[3]),
                   "r"(b[0]), "r"(b[1]));
}

#define LDW 20   // smem row stride in words

// ---------------- fp16 HMMA GEMM (proven engine; EPI 1/3/4/7) ----------------
// __launch_bounds__(512, 2): regs capped at 64 so 2 CTAs co-reside per SM.
template<int EPI, bool SPLITA, bool TRANSB>
__global__ __launch_bounds__(512, 2)
void gemm_h(const float* __restrict__ A, const float* __restrict__ A2, int lda, long long sA,
            const float* __restrict__ Bm, int ldb, long long sB,
            const float* __restrict__ bias, const float* __restrict__ bias2,
            float* __restrict__ C, long long sC,
            float* __restrict__ C2,
            const float* __restrict__ aux1, const float* __restrict__ aux2,
            const float* __restrict__ rAv, float* __restrict__ rAout,
            int Klen)
{
    __shared__ uint32_t As[2][128 * LDW];
    __shared__ uint32_t Bs[2][128 * LDW];
    __shared__ float attp[4][132];

    const int tid  = threadIdx.x;
    const int warp = tid >> 5, lane = tid & 31;
    const int wm = warp & 3, wn = warp >> 2;
    const int group = lane >> 2, tig = lane & 3;

    const bool doAtt = (EPI == 7) && (blockIdx.y < 128);
    const int  n0g  = (EPI == 3) ? blockIdx.x * 128 : 0;
    const int  m0   = (EPI == 7) ? ((blockIdx.y & 127) * 128) : (blockIdx.y * 128);
    const long long bz = blockIdx.z;
    A  += bz * sA;
    Bm += bz * sB;
    C  += bz * sC;
    if (EPI == 7 && !doAtt) Bm = aux2;

    const int ar = tid >> 2, ak2 = (tid & 3) * 4;
    const int tk2 = tid & 15, tnb = (tid >> 4) * 4;

    float acc[2][4][4];
#pragma unroll
    for (int i = 0; i < 2; i++)
#pragma unroll
        for (int j = 0; j < 4; j++)
#pragma unroll
            for (int q = 0; q < 4; q++) acc[i][j][q] = 0.f;

    float4 a0, a1, b0, b1;

    auto loadRegs = [&](int it) {
        const int k0 = it * 32;
        const float* asrc = (SPLITA && it * 32 >= 128)
            ? (A2 + (size_t)(m0 + ar) * 128 + (it * 32 - 128) + ak2 * 2)
            : (A  + (size_t)(m0 + ar) * lda + k0 + ak2 * 2);
        a0 = *(const float4*)asrc;
        a1 = *(const float4*)(asrc + 4);
        if (!TRANSB) {
            const float* bsrc = Bm + (size_t)(n0g + ar) * ldb + k0 + ak2 * 2;
            b0 = *(const float4*)bsrc;
            b1 = *(const float4*)(bsrc + 4);
        } else {
            const float* bsrc = Bm + (size_t)(k0 + 2 * tk2) * ldb + tnb;
            b0 = *(const float4*)bsrc;
            b1 = *(const float4*)(bsrc + ldb);
        }
    };

    auto stage = [&](int buf) {
        uint4 aw = { packh2(a0.x, a0.y), packh2(a0.z, a0.w),
                     packh2(a1.x, a1.y), packh2(a1.z, a1.w) };
        *(uint4*)&As[buf][ar * LDW + ak2] = aw;
        if (!TRANSB) {
            uint4 bw = { packh2(b0.x, b0.y), packh2(b0.z, b0.w),
                         packh2(b1.x, b1.y), packh2(b1.z, b1.w) };
            *(uint4*)&Bs[buf][ar * LDW + ak2] = bw;
        } else {
            Bs[buf][(tnb + 0) * LDW + tk2] = packh2(b0.x, b1.x);
            Bs[buf][(tnb + 1) * LDW + tk2] = packh2(b0.y, b1.y);
            Bs[buf][(tnb + 2) * LDW + tk2] = packh2(b0.z, b1.z);
            Bs[buf][(tnb + 3) * LDW + tk2] = packh2(b0.w, b1.w);
        }
    };

    const int niter = Klen / 32;
    loadRegs(0);
    stage(0);
    __syncthreads();

    for (int it = 0; it < niter; it++) {
        const int buf = it & 1;
        if (it + 1 < niter) loadRegs(it + 1);

#pragma unroll
        for (int s = 0; s < 2; s++) {
            const int kb = s * 8;
            uint32_t af[2][4], bf[4][2];
#pragma unroll
            for (int mi = 0; mi < 2; mi++) {
                const int m = wm * 32 + mi * 16;
                af[mi][0] = As[buf][(m + group) * LDW + kb + tig];
                af[mi][1] = As[buf][(m + group + 8) * LDW + kb + tig];
                af[mi][2] = As[buf][(m + group) * LDW + kb + tig + 4];
                af[mi][3] = As[buf][(m + group + 8) * LDW + kb + tig + 4];
            }
#pragma unroll
            for (int ni = 0; ni < 4; ni++) {
                const int n = wn * 32 + ni * 8;
                bf[ni][0] = Bs[buf][(n + group) * LDW + kb + tig];
                bf[ni][1] = Bs[buf][(n + group) * LDW + kb + tig + 4];
            }
#pragma unroll
            for (int mi = 0; mi < 2; mi++)
#pragma unroll
                for (int ni = 0; ni < 4; ni++)
                    mma_f16(acc[mi][ni], af[mi], bf[ni]);
        }

        if (it + 1 < niter) stage((it + 1) & 1);
        __syncthreads();
    }

    if (EPI == 7 && doAtt) {
        float p[4] = {0.f, 0.f, 0.f, 0.f};
#pragma unroll
        for (int mi = 0; mi < 2; mi++)
#pragma unroll
            for (int ni = 0; ni < 4; ni++) {
                const int cl = wn * 32 + ni * 8 + 2 * tig;
#pragma unroll
                for (int rr = 0; rr < 2; rr++)
#pragma unroll
                    for (int cc = 0; cc < 2; cc++) {
                        const int col = cl + cc;
                        const float v = tanhf(acc[mi][ni][rr * 2 + cc] + bias[col]);
                        p[mi * 2 + rr] += v * aux1[col];
                    }
            }
#pragma unroll
        for (int i = 0; i < 4; i++) {
            p[i] += __shfl_xor_sync(0xffffffffu, p[i], 1);
            p[i] += __shfl_xor_sync(0xffffffffu, p[i], 2);
        }
        if (tig == 0) {
#pragma unroll
            for (int mi = 0; mi < 2; mi++)
#pragma unroll
                for (int rr = 0; rr < 2; rr++)
                    attp[wn][wm * 32 + mi * 16 + group + rr * 8] = p[mi * 2 + rr];
        }
        __syncthreads();
        if (tid < 128)
            C[m0 + tid] = ((attp[0][tid] + attp[1][tid]) +
                           (attp[2][tid] + attp[3][tid])) + bias2[0];
        return;
    }

#pragma unroll
    for (int mi = 0; mi < 2; mi++) {
#pragma unroll
        for (int ni = 0; ni < 4; ni++) {
            const int cl = wn * 32 + ni * 8 + 2 * tig;
#pragma unroll
            for (int rr = 0; rr < 2; rr++) {
                const long long r = m0 + wm * 32 + mi * 16 + group + rr * 8;
#pragma unroll
                for (int cc = 0; cc < 2; cc++) {
                    float v = acc[mi][ni][rr * 2 + cc];
                    const int col  = cl + cc;
                    const int gcol = n0g + col;
                    if (EPI == 1) {
                        C[r * 128 + col] = v + bias[col];
                    } else if (EPI == 3) {
                        v = 1.f / (1.f + __expf(-(v + rAv[r] * bias[gcol] + bias2[gcol])));
                        if (blockIdx.x == 0) C2[r * 128 + col] = v * aux2[r * 128 + col];
                        else                 C [r * 128 + col] = v;
                    } else if (EPI == 4) {
                        const float h = tanhf(v + rAv[r] * bias[col] + bias2[col]);
                        const float z = aux1[r * 128 + col];
                        const float p = aux2[r * 128 + col];
                        C[r * 128 + col] = fmaf(z, h - p, p);
                    } else if (EPI == 7) {
                        C2[r * 128 + col] = tanhf(v + rAv[col]);
                    }
                }
            }
        }
    }
}

// ---------------- R6-proven fold body as device function ---------------------
__device__ void fold_dev(int x, int y, int tid,
                         const float* __restrict__ W1, const float* __restrict__ W2,
                         const float* __restrict__ W3,
                         const float* __restrict__ rW, const float* __restrict__ uW,
                         const float* __restrict__ rb, const float* __restrict__ ub,
                         const float* __restrict__ tW,
                         const float* __restrict__ attW1, const float* __restrict__ outW,
                         const float* __restrict__ cvec,
                         float* __restrict__ WrzTs, float* __restrict__ TTs,
                         float* __restrict__ W3T, float* __restrict__ attW1T,
                         float* __restrict__ outWT,
                         float* __restrict__ betarz, float* __restrict__ betah,
                         float* __restrict__ brz) {
    const float* Wpow[3] = { W1, W2, W3 };

    auto wrz = [&](int j, int n) -> float {
        return (n < 128) ? rW[j * 128 + n] : uW[j * 128 + (n - 128)];
    };

    if (y < 3) {
        const float* Ws = Wpow[y];
        float s = 0.f;
#pragma unroll 4
        for (int j = 0; j < 128; j++) s = fmaf(Ws[x * 128 + j], wrz(j, tid), s);
        WrzTs[(size_t)y * 65536 + (size_t)tid * 256 + x] = s;
    } else if (y < 6) {
        WrzTs[(size_t)(y - 3) * 65536 + (size_t)tid * 256 + 128 + x] = wrz(128 + x, tid);
    } else if (y < 9) {
        if (tid < 128) {
            const float* Ws = Wpow[y - 6];
            float s = 0.f;
#pragma unroll 4
            for (int j = 0; j < 128; j++) s = fmaf(Ws[x * 128 + j], tW[j * 128 + tid], s);
            TTs[(size_t)(y - 6) * 32768 + (size_t)tid * 256 + x] = s;
        }
    } else if (y < 12) {
        if (tid < 128)
            TTs[(size_t)(y - 9) * 32768 + (size_t)tid * 256 + 128 + x] = tW[(128 + x) * 128 + tid];
    } else if (y == 12) {
        if (tid < 128) W3T[tid * 128 + x] = W3[x * 128 + tid];
    } else if (y == 13) {
        if (tid < 128) attW1T[tid * 128 + x] = attW1[x * 128 + tid];
    } else if (y == 14) {
        if (tid < 128) outWT[tid * 128 + x] = outW[x * 128 + tid];
    } else {
        if (x < 3) {
            const float* c = cvec + x * 128;
            float s = 0.f;
#pragma unroll 4
            for (int j = 0; j < 128; j++) s = fmaf(c[j], wrz(j, tid), s);
            betarz[x * 256 + tid] = s;
            if (tid < 128) {
                float h = 0.f;
#pragma unroll 4
                for (int j = 0; j < 128; j++) h = fmaf(c[j], tW[j * 128 + tid], h);
                betah[x * 128 + tid] = h;
            }
        } else if (x == 3) {
            brz[tid] = (tid < 128) ? rb[tid] : ub[tid - 128];
        }
    }
}

// Full-chip fold launch (R6-proven shape): grid (128,16), block 256.
__global__ void k_fold(const float* __restrict__ W1, const float* __restrict__ W2,
                       const float* __restrict__ W3,
                       const float* __restrict__ rW, const float* __restrict__ uW,
                       const float* __restrict__ rb, const float* __restrict__ ub,
                       const float* __restrict__ tW,
                       const float* __restrict__ attW1, const float* __restrict__ outW,
                       const float* __restrict__ cvec,
                       float* __restrict__ WrzTs, float* __restrict__ TTs,
                       float* __restrict__ W3T, float* __restrict__ attW1T,
                       float* __restrict__ outWT,
                       float* __restrict__ betarz, float* __restrict__ betah,
                       float* __restrict__ brz) {
    fold_dev(blockIdx.x, blockIdx.y, threadIdx.x,
             W1, W2, W3, rW, uW, rb, ub, tW, attW1, outW, cvec,
             WrzTs, TTs, W3T, attW1T, outWT, betarz, betah, brz);
}

// ---------------- MEGA kernel: split-K G0 + residual riders -------------------
//   bid 0..255  : G0 GEMM split-K x2. sk=bid&1, t=bid>>1: m-tile=t&3, batch=t>>2.
//                 Klen=1024 each. All 256 CTAs co-resident at 2 CTAs/SM.
//   bid 256..275: residual-only riders (8 chunks each)
__global__ __launch_bounds__(512, 2)
void k_mega(const float* __restrict__ Amat, const float* __restrict__ edge_in,
            const float* __restrict__ prop_in,
            float* __restrict__ sp, float* __restrict__ rAp,
            float* __restrict__ part)
{
    __shared__ uint32_t As[2][128 * LDW];
    __shared__ uint32_t Bs[2][128 * LDW];

    const int bid = blockIdx.x;
    const int tid = threadIdx.x;

    if (bid >= 256) {
        const int rc = bid - 256;        // 0..19
        for (int k = 0; k < 8; k++) {
            const int rid = rc + 20 * k;
            const int b  = rid / 5;
            const int ch = (rid % 5) * 4 + (tid >> 7);
            const int d  = tid & 127;
            float s = 0.f;
            const int r0 = ch * 128;
#pragma unroll 4
            for (int r = r0; r < r0 + 128; r++) {
                if (r < Nn) s += prop_in[((long long)b * Nn + r) * Dd + d];
                else        s += edge_in[((long long)b * Ee + (r - Nn)) * Dd + d];
            }
            part[(b * 20 + ch) * Dd + d] = s;
        }
        return;
    }

    // ---- G0 GEMM CTA (split-K) ----
    const int warp = tid >> 5, lane = tid & 31;
    const int wm = warp & 3, wn = warp >> 2;
    const int group = lane >> 2, tig = lane & 3;
    const int sk = bid & 1;
    const int t  = bid >> 1;
    const int m0 = (t & 3) * 128;
    const long long bz = t >> 2;
    const int kOff = sk * (Ee / 2);
    const float* A  = Amat    + bz * (long long)Nn * Ee;
    const float* Bm = edge_in + bz * (long long)Ee * Dd;
    float* C = sp + (size_t)sk * MROWS * 128 + bz * (long long)Nn * 128;

    const int ar = tid >> 2, ak2 = (tid & 3) * 4;
    const int tk2 = tid & 15, tnb = (tid >> 4) * 4;

    float acc[2][4][4];
#pragma unroll
    for (int i = 0; i < 2; i++)
#pragma unroll
        for (int j = 0; j < 4; j++)
#pragma unroll
            for (int q = 0; q < 4; q++) acc[i][j][q] = 0.f;

    float rsum = 0.f;
    float4 a0, a1, b0, b1;

    auto loadRegs = [&](int it) {
        const int k0 = kOff + it * 32;
        const float* asrc = A + (size_t)(m0 + ar) * Ee + k0 + ak2 * 2;
        a0 = *(const float4*)asrc;
        a1 = *(const float4*)(asrc + 4);
        rsum += ((a0.x + a0.y) + (a0.z + a0.w)) + ((a1.x + a1.y) + (a1.z + a1.w));
        const float* bsrc = Bm + (size_t)(k0 + 2 * tk2) * Dd + tnb;
        b0 = *(const float4*)bsrc;
        b1 = *(const float4*)(bsrc + Dd);
    };

    auto stage = [&](int buf) {
        uint4 aw = { packh2(a0.x, a0.y), packh2(a0.z, a0.w),
                     packh2(a1.x, a1.y), packh2(a1.z, a1.w) };
        *(uint4*)&As[buf][ar * LDW + ak2] = aw;
        Bs[buf][(tnb + 0) * LDW + tk2] = packh2(b0.x, b1.x);
        Bs[buf][(tnb + 1) * LDW + tk2] = packh2(b0.y, b1.y);
        Bs[buf][(tnb + 2) * LDW + tk2] = packh2(b0.z, b1.z);
        Bs[buf][(tnb + 3) * LDW + tk2] = packh2(b0.w, b1.w);
    };

    const int niter = (Ee / 2) / 32;   // 32
    loadRegs(0);
    stage(0);
    __syncthreads();

    for (int it = 0; it < niter; it++) {
        const int buf = it & 1;
        if (it + 1 < niter) loadRegs(it + 1);

#pragma unroll
        for (int s = 0; s < 2; s++) {
            const int kb = s * 8;
            uint32_t af[2][4], bf[4][2];
#pragma unroll
            for (int mi = 0; mi < 2; mi++) {
                const int m = wm * 32 + mi * 16;
                af[mi][0] = As[buf][(m + group) * LDW + kb + tig];
                af[mi][1] = As[buf][(m + group + 8) * LDW + kb + tig];
                af[mi][2] = As[buf][(m + group) * LDW + kb + tig + 4];
                af[mi][3] = As[buf][(m + group + 8) * LDW + kb + tig + 4];
            }
#pragma unroll
            for (int ni = 0; ni < 4; ni++) {
                const int n = wn * 32 + ni * 8;
                bf[ni][0] = Bs[buf][(n + group) * LDW + kb + tig];
                bf[ni][1] = Bs[buf][(n + group) * LDW + kb + tig + 4];
            }
#pragma unroll
            for (int mi = 0; mi < 2; mi++)
#pragma unroll
                for (int ni = 0; ni < 4; ni++)
                    mma_f16(acc[mi][ni], af[mi], bf[ni]);
        }

        if (it + 1 < niter) stage((it + 1) & 1);
        __syncthreads();
    }

    {
        float s = rsum;
        s += __shfl_xor_sync(0xffffffffu, s, 1);
        s += __shfl_xor_sync(0xffffffffu, s, 2);
        if ((tid & 3) == 0)
            rAp[(long long)sk * MROWS + bz * Nn + m0 + ar] = s;
    }

#pragma unroll
    for (int mi = 0; mi < 2; mi++) {
#pragma unroll
        for (int ni = 0; ni < 4; ni++) {
            const int cl = wn * 32 + ni * 8 + 2 * tig;
#pragma unroll
            for (int rr = 0; rr < 2; rr++) {
                const long long r = m0 + wm * 32 + mi * 16 + group + rr * 8;
#pragma unroll
                for (int cc = 0; cc < 2; cc++)
                    C[r * 128 + cl + cc] = acc[mi][ni][rr * 2 + cc];
            }
        }
    }
}

// ---------------- combine split-K partials ------------------------------------
// grid 2048, block 256, float4 per thread.
__global__ void k_combine(const float* __restrict__ sp, float* __restrict__ F,
                          const float* __restrict__ rAp, float* __restrict__ rA) {
    const long long idx = (long long)blockIdx.x * 256 + threadIdx.x;   // float4 units
    const float4 x = ((const float4*)sp)[idx];
    const float4 y = ((const float4*)(sp + (size_t)MROWS * 128))[idx];
    float4 o = { x.x + y.x, x.y + y.y, x.z + y.z, x.w + y.w };
    ((float4*)F)[idx] = o;
    if (idx < MROWS) rA[idx] = rAp[idx] + rAp[MROWS + idx];
}

// ---------------- prep kernels ------------------------------------------------
__global__ void k_mm128(const float* __restrict__ A, const float* __restrict__ B,
                        float* __restrict__ C) {
    const int r = blockIdx.x, c = threadIdx.x;
    __shared__ float sA[128];
    sA[c] = A[r * 128 + c];
    __syncthreads();
    float s0 = 0.f, s1 = 0.f, s2 = 0.f, s3 = 0.f;
#pragma unroll
    for (int k = 0; k < 128; k += 4) {
        s0 = fmaf(sA[k + 0], B[(k + 0) * 128 + c], s0);
        s1 = fmaf(sA[k + 1], B[(k + 1) * 128 + c], s1);
        s2 = fmaf(sA[k + 2], B[(k + 2) * 128 + c], s2);
        s3 = fmaf(sA[k + 3], B[(k + 3) * 128 + c], s3);
    }
    C[r * 128 + c] = (s0 + s1) + (s2 + s3);
}

__global__ void k_cvec(const float* __restrict__ b, const float* __restrict__ W,
                       const float* __restrict__ W2, float* __restrict__ c) {
    const int col  = blockIdx.x * 8 + (threadIdx.x >> 5);
    const int lane = threadIdx.x & 31;
    float sw = 0.f, sw2 = 0.f;
#pragma unroll
    for (int k = lane; k < 128; k += 32) {
        const float bk = b[k];
        sw  = fmaf(bk, W [k * 128 + col], sw);
        sw2 = fmaf(bk, W2[k * 128 + col], sw2);
    }
#pragma unroll
    for (int o = 16; o; o >>= 1) {
        sw  += __shfl_xor_sync(0xffffffffu, sw, o);
        sw2 += __shfl_xor_sync(0xffffffffu, sw2, o);
    }
    if (lane == 0) {
        const float bc = b[col];
        c[col]       = bc;
        c[128 + col] = bc + sw;
        c[256 + col] = bc + sw + sw2;
    }
}

// ---------------- misc kernels -------------------------------------------------
__global__ void k_final(const float* __restrict__ att, const float* __restrict__ outn,
                        const float* __restrict__ part,
                        float* __restrict__ d_res, float* __restrict__ d_mul) {
    const int b = blockIdx.x, d = threadIdx.x;
    __shared__ float sa[Nn];
    __shared__ float red[128];
    float lm = -1e30f;
#pragma unroll
    for (int i = 0; i < 4; i++) {
        const float v = att[b * Nn + d + i * 128];
        sa[d + i * 128] = v;
        lm = fmaxf(lm, v);
    }
    red[d] = lm;
    __syncthreads();
    for (int s = 64; s; s >>= 1) { if (d < s) red[d] = fmaxf(red[d], red[d + s]); __syncthreads(); }
    const float M = red[0];
    __syncthreads();
    float ls = 0.f;
#pragma unroll
    for (int i = 0; i < 4; i++) {
        const float e = __expf(sa[d + i * 128] - M);
        sa[d + i * 128] = e;
        ls += e;
    }
    red[d] = ls;
    __syncthreads();
    for (int s = 64; s; s >>= 1) { if (d < s) red[d] += red[d + s]; __syncthreads(); }
    const float S = red[0];
    __syncthreads();

    const float* ob = outn + (long long)b * Nn * Dd;
    float acc = 0.f;
#pragma unroll 8
    for (int n = 0; n < Nn; n++) acc = fmaf(sa[n], ob[n * Dd + d], acc);
    acc /= S;
    float resid = 0.f;
#pragma unroll
    for (int c = 0; c < 20; c++) resid += part[(b * 20 + c) * Dd + d];
    resid *= (1.f / 2560.f);
    d_mul[b * Dd + d] = acc;
    d_res[b * Dd + d] = fmaxf(tanhf(acc) + resid, 0.f);
}

// ---------------- host launch ----------------------------------------------------
static float* sym(const void* s) { void* p = nullptr; cudaGetSymbolAddress(&p, s); return (float*)p; }

extern "C" void kernel_launch(void* const* d_in, const int* in_sizes, int n_in,
                              void* d_out, int out_size) {
    const float* prop_in = (const float*)d_in[0];
    const float* edge_in = (const float*)d_in[1];
    const float* Amat    = (const float*)d_in[2];
    const float* link_W  = (const float*)d_in[4];
    const float* link_b  = (const float*)d_in[5];
    const float* reset_W = (const float*)d_in[6];
    const float* reset_b = (const float*)d_in[7];
    const float* upd_W   = (const float*)d_in[8];
    const float* upd_b   = (const float*)d_in[9];
    const float* trans_W = (const float*)d_in[10];
    const float* trans_b = (const float*)d_in[11];
    const float* att_W1  = (const float*)d_in[12];
    const float* att_b1  = (const float*)d_in[13];
    const float* att_W2  = (const float*)d_in[14];
    const float* att_b2  = (const float*)d_in[15];
    const float* out_W   = (const float*)d_in[16];
    const float* out_b   = (const float*)d_in[17];

    float* out      = (float*)d_out;
    float* out_res  = out;
    float* out_mul  = out + Bb * Dd;
    float* out_edge = out + 2 * Bb * Dd;

    float* G0 = sym(g_G0); float* split = sym(g_split); float* rAp = sym(g_rAp);
    float* prop = sym(g_prop); float* rp = sym(g_rp);
    float* zbuf = sym(g_zbuf); float* outn = sym(g_outn); float* rA = sym(g_rA);
    float* WrzTs = sym(g_WrzTs); float* TTs = sym(g_TTs);
    float* betarz = sym(g_betarz); float* betah = sym(g_betah); float* brz = sym(g_brz);
    float* attW1T = sym(g_attW1T); float* outWT = sym(g_outWT);
    float* W2 = sym(g_W2); float* W3 = sym(g_W3); float* W3T = sym(g_W3T);
    float* cvec = sym(g_c);
    float* att = sym(g_att); float* part = sym(g_part);

    // --- tiny serial prep (fold inputs) ---
    k_mm128<<<128, 128>>>(link_W, link_W, W2);
    k_mm128<<<128, 128>>>(W2, link_W, W3);
    k_cvec<<<16, 256>>>(link_b, link_W, W2, cvec);

    // --- MEGA: split-K x2 G0 (256 CTAs, all co-resident) + residual riders ---
    k_mega<<<276, 512>>>(Amat, edge_in, prop_in, split, rAp, part);

    // --- fold: full-chip launch ---
    k_fold<<<dim3(128, 16), 256>>>(link_W, W2, W3, reset_W, upd_W, reset_b, upd_b,
                                   trans_W, att_W1, out_W, cvec,
                                   WrzTs, TTs, W3T, attW1T, outWT,
                                   betarz, betah, brz);

    // --- combine split-K partials ---
    k_combine<<<2048, 256>>>(split, G0, rAp, rA);

    // edge_states output: e3 = e0 @ W3 + c3
    gemm_h<1, false, false><<<dim3(1, (Bb * Ee) / 128, 1), 512>>>(
        edge_in, nullptr, 128, 0, W3T, 128, 0, cvec + 256, nullptr,
        out_edge, 0, nullptr, nullptr, nullptr, nullptr, nullptr, 128);

    // --- 3 GRU steps ---
    const float* prop_cur = prop_in;
    for (int s = 0; s < NSTEP; s++) {
        gemm_h<3, true, false><<<dim3(2, MROWS / 128, 1), 512>>>(
            G0, prop_cur, 128, 0, WrzTs + (size_t)s * 65536, 256, 0,
            betarz + s * 256, brz,
            zbuf, 0, rp, nullptr, prop_cur, rA, nullptr, 256);
        gemm_h<4, true, false><<<dim3(1, MROWS / 128, 1), 512>>>(
            G0, rp, 128, 0, TTs + (size_t)s * 32768, 256, 0,
            betah + s * 128, trans_b,
            prop, 0, nullptr, zbuf, prop_cur, rA, nullptr, 256);
        prop_cur = prop;
    }

    // --- merged epilogue GEMM: by<128 att score, by>=128 outn ---
    gemm_h<7, false, false><<<dim3(1, 256, 1), 512>>>(
        prop, nullptr, 128, 0, attW1T, 128, 0, att_b1, att_b2,
        att, 0, outn, att_W2, outWT, out_b, nullptr, 128);

    k_final<<<Bb, Dd>>>(att, outn, part, out_res, out_mul);
}

// round 15
// speedup vs baseline: 1.2105x; 1.2105x over previous
#include <cuda_runtime.h>
#include <cuda_fp16.h>
#include <math.h>
#include <stdint.h>

#define Bb 32
#define Nn 512
#define Ee 2048
#define Dd 128
#define NSTEP 3
#define MROWS (Bb*Nn)          // 16384

// ---------------- scratch (device globals: allocation-free) ----------------
__device__ float g_G0   [MROWS*Dd];
__device__ float g_prop [MROWS*Dd];
__device__ float g_rp   [MROWS*Dd];
__device__ float g_zbuf [MROWS*Dd];
__device__ float g_outn [MROWS*Dd];
__device__ float g_rA   [MROWS];
__device__ float g_WrzTs[3*256*256];    // per-step folded [N=256][K=256]
__device__ float g_TTs  [3*Dd*256];     // per-step folded [N=128][K=256]
__device__ float g_betarz[3*256];
__device__ float g_betah [3*Dd];
__device__ float g_brz  [256];
__device__ float g_attW1T[Dd*Dd];
__device__ float g_outWT [Dd*Dd];
__device__ float g_W2   [Dd*Dd];
__device__ float g_W3   [Dd*Dd];
__device__ float g_W3T  [Dd*Dd];
__device__ float g_c    [3*Dd];
__device__ float g_att  [Bb*Nn];
__device__ float g_part [Bb*20*Dd];

// ---------------- fp16 mma helpers ------------------------------------------
__device__ __forceinline__ uint32_t packh2(float x, float y) {
    __half2 h = __floats2half2_rn(x, y);
    return *(uint32_t*)&h;
}
__device__ __forceinline__ void mma_f16(float* c, const uint32_t* a, const uint32_t* b) {
    asm volatile("mma.sync.aligned.m16n8k16.row.col.f32.f16.f16.f32 "
                 "{%0,%1,%2,%3},{%4,%5,%6,%7},{%8,%9},{%0,%1,%2,%3};"
                 : "+f"(c[0]), "+f"(c[1]), "+f"(c[2]), "+f"(c[3])
                 : "r"(a[0]), "r"(a[1]), "r"(a[2]), "r"(a[3]),
                   "r"(b[0]), "r"(b[1]));
}

#define LDW 20   // smem row stride in words

// ---------------- fp16 HMMA GEMM (R12-proven engine; EPI 1/3/4/7) ------------
template<int EPI, bool SPLITA, bool TRANSB>
__global__ __launch_bounds__(512)
void gemm_h(const float* __restrict__ A, const float* __restrict__ A2, int lda, long long sA,
            const float* __restrict__ Bm, int ldb, long long sB,
            const float* __restrict__ bias, const float* __restrict__ bias2,
            float* __restrict__ C, long long sC,
            float* __restrict__ C2,
            const float* __restrict__ aux1, const float* __restrict__ aux2,
            const float* __restrict__ rAv, float* __restrict__ rAout,
            int Klen)
{
    __shared__ uint32_t As[2][128 * LDW];
    __shared__ uint32_t Bs[2][128 * LDW];
    __shared__ float attp[4][132];

    const int tid  = threadIdx.x;
    const int warp = tid >> 5, lane = tid & 31;
    const int wm = warp & 3, wn = warp >> 2;
    const int group = lane >> 2, tig = lane & 3;

    const bool doAtt = (EPI == 7) && (blockIdx.y < 128);
    const int  n0g  = (EPI == 3) ? blockIdx.x * 128 : 0;
    const int  m0   = (EPI == 7) ? ((blockIdx.y & 127) * 128) : (blockIdx.y * 128);
    const long long bz = blockIdx.z;
    A  += bz * sA;
    Bm += bz * sB;
    C  += bz * sC;
    if (EPI == 7 && !doAtt) Bm = aux2;

    const int ar = tid >> 2, ak2 = (tid & 3) * 4;
    const int tk2 = tid & 15, tnb = (tid >> 4) * 4;

    float acc[2][4][4];
#pragma unroll
    for (int i = 0; i < 2; i++)
#pragma unroll
        for (int j = 0; j < 4; j++)
#pragma unroll
            for (int q = 0; q < 4; q++) acc[i][j][q] = 0.f;

    float4 a0, a1, b0, b1;

    auto loadRegs = [&](int it) {
        const int k0 = it * 32;
        const float* asrc = (SPLITA && it * 32 >= 128)
            ? (A2 + (size_t)(m0 + ar) * 128 + (it * 32 - 128) + ak2 * 2)
            : (A  + (size_t)(m0 + ar) * lda + k0 + ak2 * 2);
        a0 = *(const float4*)asrc;
        a1 = *(const float4*)(asrc + 4);
        if (!TRANSB) {
            const float* bsrc = Bm + (size_t)(n0g + ar) * ldb + k0 + ak2 * 2;
            b0 = *(const float4*)bsrc;
            b1 = *(const float4*)(bsrc + 4);
        } else {
            const float* bsrc = Bm + (size_t)(k0 + 2 * tk2) * ldb + tnb;
            b0 = *(const float4*)bsrc;
            b1 = *(const float4*)(bsrc + ldb);
        }
    };

    auto stage = [&](int buf) {
        uint4 aw = { packh2(a0.x, a0.y), packh2(a0.z, a0.w),
                     packh2(a1.x, a1.y), packh2(a1.z, a1.w) };
        *(uint4*)&As[buf][ar * LDW + ak2] = aw;
        if (!TRANSB) {
            uint4 bw = { packh2(b0.x, b0.y), packh2(b0.z, b0.w),
                         packh2(b1.x, b1.y), packh2(b1.z, b1.w) };
            *(uint4*)&Bs[buf][ar * LDW + ak2] = bw;
        } else {
            Bs[buf][(tnb + 0) * LDW + tk2] = packh2(b0.x, b1.x);
            Bs[buf][(tnb + 1) * LDW + tk2] = packh2(b0.y, b1.y);
            Bs[buf][(tnb + 2) * LDW + tk2] = packh2(b0.z, b1.z);
            Bs[buf][(tnb + 3) * LDW + tk2] = packh2(b0.w, b1.w);
        }
    };

    const int niter = Klen / 32;
    loadRegs(0);
    stage(0);
    __syncthreads();

    for (int it = 0; it < niter; it++) {
        const int buf = it & 1;
        if (it + 1 < niter) loadRegs(it + 1);

#pragma unroll
        for (int s = 0; s < 2; s++) {
            const int kb = s * 8;
            uint32_t af[2][4], bf[4][2];
#pragma unroll
            for (int mi = 0; mi < 2; mi++) {
                const int m = wm * 32 + mi * 16;
                af[mi][0] = As[buf][(m + group) * LDW + kb + tig];
                af[mi][1] = As[buf][(m + group + 8) * LDW + kb + tig];
                af[mi][2] = As[buf][(m + group) * LDW + kb + tig + 4];
                af[mi][3] = As[buf][(m + group + 8) * LDW + kb + tig + 4];
            }
#pragma unroll
            for (int ni = 0; ni < 4; ni++) {
                const int n = wn * 32 + ni * 8;
                bf[ni][0] = Bs[buf][(n + group) * LDW + kb + tig];
                bf[ni][1] = Bs[buf][(n + group) * LDW + kb + tig + 4];
            }
#pragma unroll
            for (int mi = 0; mi < 2; mi++)
#pragma unroll
                for (int ni = 0; ni < 4; ni++)
                    mma_f16(acc[mi][ni], af[mi], bf[ni]);
        }

        if (it + 1 < niter) stage((it + 1) & 1);
        __syncthreads();
    }

    if (EPI == 7 && doAtt) {
        float p[4] = {0.f, 0.f, 0.f, 0.f};
#pragma unroll
        for (int mi = 0; mi < 2; mi++)
#pragma unroll
            for (int ni = 0; ni < 4; ni++) {
                const int cl = wn * 32 + ni * 8 + 2 * tig;
#pragma unroll
                for (int rr = 0; rr < 2; rr++)
#pragma unroll
                    for (int cc = 0; cc < 2; cc++) {
                        const int col = cl + cc;
                        const float v = tanhf(acc[mi][ni][rr * 2 + cc] + bias[col]);
                        p[mi * 2 + rr] += v * aux1[col];
                    }
            }
#pragma unroll
        for (int i = 0; i < 4; i++) {
            p[i] += __shfl_xor_sync(0xffffffffu, p[i], 1);
            p[i] += __shfl_xor_sync(0xffffffffu, p[i], 2);
        }
        if (tig == 0) {
#pragma unroll
            for (int mi = 0; mi < 2; mi++)
#pragma unroll
                for (int rr = 0; rr < 2; rr++)
                    attp[wn][wm * 32 + mi * 16 + group + rr * 8] = p[mi * 2 + rr];
        }
        __syncthreads();
        if (tid < 128)
            C[m0 + tid] = ((attp[0][tid] + attp[1][tid]) +
                           (attp[2][tid] + attp[3][tid])) + bias2[0];
        return;
    }

#pragma unroll
    for (int mi = 0; mi < 2; mi++) {
#pragma unroll
        for (int ni = 0; ni < 4; ni++) {
            const int cl = wn * 32 + ni * 8 + 2 * tig;
#pragma unroll
            for (int rr = 0; rr < 2; rr++) {
                const long long r = m0 + wm * 32 + mi * 16 + group + rr * 8;
#pragma unroll
                for (int cc = 0; cc < 2; cc++) {
                    float v = acc[mi][ni][rr * 2 + cc];
                    const int col  = cl + cc;
                    const int gcol = n0g + col;
                    if (EPI == 1) {
                        C[r * 128 + col] = v + bias[col];
                    } else if (EPI == 3) {
                        v = 1.f / (1.f + __expf(-(v + rAv[r] * bias[gcol] + bias2[gcol])));
                        if (blockIdx.x == 0) C2[r * 128 + col] = v * aux2[r * 128 + col];
                        else                 C [r * 128 + col] = v;
                    } else if (EPI == 4) {
                        const float h = tanhf(v + rAv[r] * bias[col] + bias2[col]);
                        const float z = aux1[r * 128 + col];
                        const float p = aux2[r * 128 + col];
                        C[r * 128 + col] = fmaf(z, h - p, p);
                    } else if (EPI == 7) {
                        C2[r * 128 + col] = tanhf(v + rAv[col]);
                    }
                }
            }
        }
    }
}

// ---------------- R6-proven fold body as device function ---------------------
__device__ void fold_dev(int x, int y, int tid,
                         const float* __restrict__ W1, const float* __restrict__ W2,
                         const float* __restrict__ W3,
                         const float* __restrict__ rW, const float* __restrict__ uW,
                         const float* __restrict__ rb, const float* __restrict__ ub,
                         const float* __restrict__ tW,
                         const float* __restrict__ attW1, const float* __restrict__ outW,
                         const float* __restrict__ cvec,
                         float* __restrict__ WrzTs, float* __restrict__ TTs,
                         float* __restrict__ W3T, float* __restrict__ attW1T,
                         float* __restrict__ outWT,
                         float* __restrict__ betarz, float* __restrict__ betah,
                         float* __restrict__ brz) {
    const float* Wpow[3] = { W1, W2, W3 };

    auto wrz = [&](int j, int n) -> float {
        return (n < 128) ? rW[j * 128 + n] : uW[j * 128 + (n - 128)];
    };

    if (y < 3) {
        const float* Ws = Wpow[y];
        float s = 0.f;
#pragma unroll 4
        for (int j = 0; j < 128; j++) s = fmaf(Ws[x * 128 + j], wrz(j, tid), s);
        WrzTs[(size_t)y * 65536 + (size_t)tid * 256 + x] = s;
    } else if (y < 6) {
        WrzTs[(size_t)(y - 3) * 65536 + (size_t)tid * 256 + 128 + x] = wrz(128 + x, tid);
    } else if (y < 9) {
        if (tid < 128) {
            const float* Ws = Wpow[y - 6];
            float s = 0.f;
#pragma unroll 4
            for (int j = 0; j < 128; j++) s = fmaf(Ws[x * 128 + j], tW[j * 128 + tid], s);
            TTs[(size_t)(y - 6) * 32768 + (size_t)tid * 256 + x] = s;
        }
    } else if (y < 12) {
        if (tid < 128)
            TTs[(size_t)(y - 9) * 32768 + (size_t)tid * 256 + 128 + x] = tW[(128 + x) * 128 + tid];
    } else if (y == 12) {
        if (tid < 128) W3T[tid * 128 + x] = W3[x * 128 + tid];
    } else if (y == 13) {
        if (tid < 128) attW1T[tid * 128 + x] = attW1[x * 128 + tid];
    } else if (y == 14) {
        if (tid < 128) outWT[tid * 128 + x] = outW[x * 128 + tid];
    } else {
        if (x < 3) {
            const float* c = cvec + x * 128;
            float s = 0.f;
#pragma unroll 4
            for (int j = 0; j < 128; j++) s = fmaf(c[j], wrz(j, tid), s);
            betarz[x * 256 + tid] = s;
            if (tid < 128) {
                float h = 0.f;
#pragma unroll 4
                for (int j = 0; j < 128; j++) h = fmaf(c[j], tW[j * 128 + tid], h);
                betah[x * 128 + tid] = h;
            }
        } else if (x == 3) {
            brz[tid] = (tid < 128) ? rb[tid] : ub[tid - 128];
        }
    }
}

// Full-chip fold launch (R6-proven shape): grid (128,16), block 256.
__global__ void k_fold(const float* __restrict__ W1, const float* __restrict__ W2,
                       const float* __restrict__ W3,
                       const float* __restrict__ rW, const float* __restrict__ uW,
                       const float* __restrict__ rb, const float* __restrict__ ub,
                       const float* __restrict__ tW,
                       const float* __restrict__ attW1, const float* __restrict__ outW,
                       const float* __restrict__ cvec,
                       float* __restrict__ WrzTs, float* __restrict__ TTs,
                       float* __restrict__ W3T, float* __restrict__ attW1T,
                       float* __restrict__ outWT,
                       float* __restrict__ betarz, float* __restrict__ betah,
                       float* __restrict__ brz) {
    fold_dev(blockIdx.x, blockIdx.y, threadIdx.x,
             W1, W2, W3, rW, uW, rb, ub, tW, attW1, outW, cvec,
             WrzTs, TTs, W3T, attW1T, outWT, betarz, betah, brz);
}

// ---------------- MEGA kernel: 148 CTAs, single wave -------------------------
//   bid 0..127  : G0 GEMM (m-tile = bid&3, batch = bid>>2) + rowsum(A)
//                 distance-2 register prefetch (two staging sets, unroll x2)
//   bid 128..147: residual-only riders (8 chunks each, inside GEMM shadow)
__global__ __launch_bounds__(512)
void k_mega(const float* __restrict__ Amat, const float* __restrict__ edge_in,
            const float* __restrict__ prop_in,
            float* __restrict__ G0, float* __restrict__ rAout,
            float* __restrict__ part)
{
    __shared__ uint32_t As[2][128 * LDW];
    __shared__ uint32_t Bs[2][128 * LDW];

    const int bid = blockIdx.x;
    const int tid = threadIdx.x;

    if (bid >= 128) {
        const int rc = bid - 128;        // 0..19
        for (int k = 0; k < 8; k++) {
            const int rid = rc + 20 * k;
            const int b  = rid / 5;
            const int ch = (rid % 5) * 4 + (tid >> 7);
            const int d  = tid & 127;
            float s = 0.f;
            const int r0 = ch * 128;
#pragma unroll 4
            for (int r = r0; r < r0 + 128; r++) {
                if (r < Nn) s += prop_in[((long long)b * Nn + r) * Dd + d];
                else        s += edge_in[((long long)b * Ee + (r - Nn)) * Dd + d];
            }
            part[(b * 20 + ch) * Dd + d] = s;
        }
        return;
    }

    // ---- G0 GEMM CTA ----
    const int warp = tid >> 5, lane = tid & 31;
    const int wm = warp & 3, wn = warp >> 2;
    const int group = lane >> 2, tig = lane & 3;
    const int m0 = (bid & 3) * 128;
    const long long bz = bid >> 2;
    const float* A  = Amat    + bz * (long long)Nn * Ee;
    const float* Bm = edge_in + bz * (long long)Ee * Dd;
    float* C = G0 + bz * (long long)Nn * 128;

    const int ar = tid >> 2, ak2 = (tid & 3) * 4;
    const int tk2 = tid & 15, tnb = (tid >> 4) * 4;

    float acc[2][4][4];
#pragma unroll
    for (int i = 0; i < 2; i++)
#pragma unroll
        for (int j = 0; j < 4; j++)
#pragma unroll
            for (int q = 0; q < 4; q++) acc[i][j][q] = 0.f;

    float rsum = 0.f;
    // two register staging sets (distance-2 prefetch)
    float4 a0A, a1A, b0A, b1A;
    float4 a0B, a1B, b0B, b1B;

    const int niter = Ee / 32;   // 64 (even)

    auto loadTo = [&](int it, float4& a0, float4& a1, float4& b0, float4& b1) {
        if (it >= niter) return;
        const int k0 = it * 32;
        const float* asrc = A + (size_t)(m0 + ar) * Ee + k0 + ak2 * 2;
        a0 = *(const float4*)asrc;
        a1 = *(const float4*)(asrc + 4);
        rsum += ((a0.x + a0.y) + (a0.z + a0.w)) + ((a1.x + a1.y) + (a1.z + a1.w));
        const float* bsrc = Bm + (size_t)(k0 + 2 * tk2) * Dd + tnb;
        b0 = *(const float4*)bsrc;
        b1 = *(const float4*)(bsrc + Dd);
    };

    auto stageFrom = [&](int buf, const float4& a0, const float4& a1,
                         const float4& b0, const float4& b1) {
        uint4 aw = { packh2(a0.x, a0.y), packh2(a0.z, a0.w),
                     packh2(a1.x, a1.y), packh2(a1.z, a1.w) };
        *(uint4*)&As[buf][ar * LDW + ak2] = aw;
        Bs[buf][(tnb + 0) * LDW + tk2] = packh2(b0.x, b1.x);
        Bs[buf][(tnb + 1) * LDW + tk2] = packh2(b0.y, b1.y);
        Bs[buf][(tnb + 2) * LDW + tk2] = packh2(b0.z, b1.z);
        Bs[buf][(tnb + 3) * LDW + tk2] = packh2(b0.w, b1.w);
    };

    auto compute = [&](int buf) {
#pragma unroll
        for (int s = 0; s < 2; s++) {
            const int kb = s * 8;
            uint32_t af[2][4], bf[4][2];
#pragma unroll
            for (int mi = 0; mi < 2; mi++) {
                const int m = wm * 32 + mi * 16;
                af[mi][0] = As[buf][(m + group) * LDW + kb + tig];
                af[mi][1] = As[buf][(m + group + 8) * LDW + kb + tig];
                af[mi][2] = As[buf][(m + group) * LDW + kb + tig + 4];
                af[mi][3] = As[buf][(m + group + 8) * LDW + kb + tig + 4];
            }
#pragma unroll
            for (int ni = 0; ni < 4; ni++) {
                const int n = wn * 32 + ni * 8;
                bf[ni][0] = Bs[buf][(n + group) * LDW + kb + tig];
                bf[ni][1] = Bs[buf][(n + group) * LDW + kb + tig + 4];
            }
#pragma unroll
            for (int mi = 0; mi < 2; mi++)
#pragma unroll
                for (int ni = 0; ni < 4; ni++)
                    mma_f16(acc[mi][ni], af[mi], bf[ni]);
        }
    };

    // prologue: load iters 0,1; stage iter 0 into buf0
    loadTo(0, a0A, a1A, b0A, b1A);
    loadTo(1, a0B, a1B, b0B, b1B);
    stageFrom(0, a0A, a1A, b0A, b1A);
    __syncthreads();

    for (int it = 0; it < niter; it += 2) {
        // even half: compute iter it (buf0); prefetch it+2 into set A; stage it+1
        loadTo(it + 2, a0A, a1A, b0A, b1A);
        compute(0);
        stageFrom(1, a0B, a1B, b0B, b1B);     // iter it+1 (< niter, niter even)
        __syncthreads();
        // odd half: compute iter it+1 (buf1); prefetch it+3 into set B; stage it+2
        loadTo(it + 3, a0B, a1B, b0B, b1B);
        compute(1);
        if (it + 2 < niter) {
            stageFrom(0, a0A, a1A, b0A, b1A); // iter it+2
            __syncthreads();
        }
    }

    {
        float s = rsum;
        s += __shfl_xor_sync(0xffffffffu, s, 1);
        s += __shfl_xor_sync(0xffffffffu, s, 2);
        if ((tid & 3) == 0)
            rAout[bz * Nn + m0 + ar] = s;
    }

#pragma unroll
    for (int mi = 0; mi < 2; mi++) {
#pragma unroll
        for (int ni = 0; ni < 4; ni++) {
            const int cl = wn * 32 + ni * 8 + 2 * tig;
#pragma unroll
            for (int rr = 0; rr < 2; rr++) {
                const long long r = m0 + wm * 32 + mi * 16 + group + rr * 8;
#pragma unroll
                for (int cc = 0; cc < 2; cc++)
                    C[r * 128 + cl + cc] = acc[mi][ni][rr * 2 + cc];
            }
        }
    }
}

// ---------------- prep kernels ------------------------------------------------
__global__ void k_mm128(const float* __restrict__ A, const float* __restrict__ B,
                        float* __restrict__ C) {
    const int r = blockIdx.x, c = threadIdx.x;
    __shared__ float sA[128];
    sA[c] = A[r * 128 + c];
    __syncthreads();
    float s0 = 0.f, s1 = 0.f, s2 = 0.f, s3 = 0.f;
#pragma unroll
    for (int k = 0; k < 128; k += 4) {
        s0 = fmaf(sA[k + 0], B[(k + 0) * 128 + c], s0);
        s1 = fmaf(sA[k + 1], B[(k + 1) * 128 + c], s1);
        s2 = fmaf(sA[k + 2], B[(k + 2) * 128 + c], s2);
        s3 = fmaf(sA[k + 3], B[(k + 3) * 128 + c], s3);
    }
    C[r * 128 + c] = (s0 + s1) + (s2 + s3);
}

__global__ void k_cvec(const float* __restrict__ b, const float* __restrict__ W,
                       const float* __restrict__ W2, float* __restrict__ c) {
    const int col  = blockIdx.x * 8 + (threadIdx.x >> 5);
    const int lane = threadIdx.x & 31;
    float sw = 0.f, sw2 = 0.f;
#pragma unroll
    for (int k = lane; k < 128; k += 32) {
        const float bk = b[k];
        sw  = fmaf(bk, W [k * 128 + col], sw);
        sw2 = fmaf(bk, W2[k * 128 + col], sw2);
    }
#pragma unroll
    for (int o = 16; o; o >>= 1) {
        sw  += __shfl_xor_sync(0xffffffffu, sw, o);
        sw2 += __shfl_xor_sync(0xffffffffu, sw2, o);
    }
    if (lane == 0) {
        const float bc = b[col];
        c[col]       = bc;
        c[128 + col] = bc + sw;
        c[256 + col] = bc + sw + sw2;
    }
}

// ---------------- misc kernels -------------------------------------------------
__global__ void k_final(const float* __restrict__ att, const float* __restrict__ outn,
                        const float* __restrict__ part,
                        float* __restrict__ d_res, float* __restrict__ d_mul) {
    const int b = blockIdx.x, d = threadIdx.x;
    __shared__ float sa[Nn];
    __shared__ float red[128];
    float lm = -1e30f;
#pragma unroll
    for (int i = 0; i < 4; i++) {
        const float v = att[b * Nn + d + i * 128];
        sa[d + i * 128] = v;
        lm = fmaxf(lm, v);
    }
    red[d] = lm;
    __syncthreads();
    for (int s = 64; s; s >>= 1) { if (d < s) red[d] = fmaxf(red[d], red[d + s]); __syncthreads(); }
    const float M = red[0];
    __syncthreads();
    float ls = 0.f;
#pragma unroll
    for (int i = 0; i < 4; i++) {
        const float e = __expf(sa[d + i * 128] - M);
        sa[d + i * 128] = e;
        ls += e;
    }
    red[d] = ls;
    __syncthreads();
    for (int s = 64; s; s >>= 1) { if (d < s) red[d] += red[d + s]; __syncthreads(); }
    const float S = red[0];
    __syncthreads();

    const float* ob = outn + (long long)b * Nn * Dd;
    float acc = 0.f;
#pragma unroll 8
    for (int n = 0; n < Nn; n++) acc = fmaf(sa[n], ob[n * Dd + d], acc);
    acc /= S;
    float resid = 0.f;
#pragma unroll
    for (int c = 0; c < 20; c++) resid += part[(b * 20 + c) * Dd + d];
    resid *= (1.f / 2560.f);
    d_mul[b * Dd + d] = acc;
    d_res[b * Dd + d] = fmaxf(tanhf(acc) + resid, 0.f);
}

// ---------------- host launch ----------------------------------------------------
static float* sym(const void* s) { void* p = nullptr; cudaGetSymbolAddress(&p, s); return (float*)p; }

extern "C" void kernel_launch(void* const* d_in, const int* in_sizes, int n_in,
                              void* d_out, int out_size) {
    const float* prop_in = (const float*)d_in[0];
    const float* edge_in = (const float*)d_in[1];
    const float* Amat    = (const float*)d_in[2];
    const float* link_W  = (const float*)d_in[4];
    const float* link_b  = (const float*)d_in[5];
    const float* reset_W = (const float*)d_in[6];
    const float* reset_b = (const float*)d_in[7];
    const float* upd_W   = (const float*)d_in[8];
    const float* upd_b   = (const float*)d_in[9];
    const float* trans_W = (const float*)d_in[10];
    const float* trans_b = (const float*)d_in[11];
    const float* att_W1  = (const float*)d_in[12];
    const float* att_b1  = (const float*)d_in[13];
    const float* att_W2  = (const float*)d_in[14];
    const float* att_b2  = (const float*)d_in[15];
    const float* out_W   = (const float*)d_in[16];
    const float* out_b   = (const float*)d_in[17];

    float* out      = (float*)d_out;
    float* out_res  = out;
    float* out_mul  = out + Bb * Dd;
    float* out_edge = out + 2 * Bb * Dd;

    float* G0 = sym(g_G0); float* prop = sym(g_prop); float* rp = sym(g_rp);
    float* zbuf = sym(g_zbuf); float* outn = sym(g_outn); float* rA = sym(g_rA);
    float* WrzTs = sym(g_WrzTs); float* TTs = sym(g_TTs);
    float* betarz = sym(g_betarz); float* betah = sym(g_betah); float* brz = sym(g_brz);
    float* attW1T = sym(g_attW1T); float* outWT = sym(g_outWT);
    float* W2 = sym(g_W2); float* W3 = sym(g_W3); float* W3T = sym(g_W3T);
    float* cvec = sym(g_c);
    float* att = sym(g_att); float* part = sym(g_part);

    // --- tiny serial prep (fold inputs) ---
    k_mm128<<<128, 128>>>(link_W, link_W, W2);
    k_mm128<<<128, 128>>>(W2, link_W, W3);
    k_cvec<<<16, 256>>>(link_b, link_W, W2, cvec);

    // --- MEGA: 148 CTAs, one wave. G0 GEMM (dist-2 prefetch) + residual riders ---
    k_mega<<<148, 512>>>(Amat, edge_in, prop_in, G0, rA, part);

    // --- fold: full-chip launch ---
    k_fold<<<dim3(128, 16), 256>>>(link_W, W2, W3, reset_W, upd_W, reset_b, upd_b,
                                   trans_W, att_W1, out_W, cvec,
                                   WrzTs, TTs, W3T, attW1T, outWT,
                                   betarz, betah, brz);

    // edge_states output: e3 = e0 @ W3 + c3
    gemm_h<1, false, false><<<dim3(1, (Bb * Ee) / 128, 1), 512>>>(
        edge_in, nullptr, 128, 0, W3T, 128, 0, cvec + 256, nullptr,
        out_edge, 0, nullptr, nullptr, nullptr, nullptr, nullptr, 128);

    // --- 3 GRU steps ---
    const float* prop_cur = prop_in;
    for (int s = 0; s < NSTEP; s++) {
        gemm_h<3, true, false><<<dim3(2, MROWS / 128, 1), 512>>>(
            G0, prop_cur, 128, 0, WrzTs + (size_t)s * 65536, 256, 0,
            betarz + s * 256, brz,
            zbuf, 0, rp, nullptr, prop_cur, rA, nullptr, 256);
        gemm_h<4, true, false><<<dim3(1, MROWS / 128, 1), 512>>>(
            G0, rp, 128, 0, TTs + (size_t)s * 32768, 256, 0,
            betah + s * 128, trans_b,
            prop, 0, nullptr, zbuf, prop_cur, rA, nullptr, 256);
        prop_cur = prop;
    }

    // --- merged epilogue GEMM: by<128 att score, by>=128 outn ---
    gemm_h<7, false, false><<<dim3(1, 256, 1), 512>>>(
        prop, nullptr, 128, 0, attW1T, 128, 0, att_b1, att_b2,
        att, 0, outn, att_W2, outWT, out_b, nullptr, 128);

    k_final<<<Bb, Dd>>>(att, outn, part, out_res, out_mul);
}

// round 16
// speedup vs baseline: 1.2299x; 1.0161x over previous
#include <cuda_runtime.h>
#include <cuda_fp16.h>
#include <math.h>
#include <stdint.h>

#define Bb 32
#define Nn 512
#define Ee 2048
#define Dd 128
#define NSTEP 3
#define MROWS (Bb*Nn)          // 16384

// ---------------- scratch (device globals: allocation-free) ----------------
__device__ float g_G0   [MROWS*Dd];
__device__ float g_prop [MROWS*Dd];
__device__ float g_rp   [MROWS*Dd];
__device__ float g_zbuf [MROWS*Dd];
__device__ float g_outn [MROWS*Dd];
__device__ float g_rA   [MROWS];
__device__ float g_WrzTs[3*256*256];    // per-step folded [N=256][K=256]
__device__ float g_TTs  [3*Dd*256];     // per-step folded [N=128][K=256]
__device__ float g_betarz[3*256];
__device__ float g_betah [3*Dd];
__device__ float g_brz  [256];
__device__ float g_attW1T[Dd*Dd];
__device__ float g_outWT [Dd*Dd];
__device__ float g_W2   [Dd*Dd];
__device__ float g_W3   [Dd*Dd];
__device__ float g_W3T  [Dd*Dd];
__device__ float g_c    [3*Dd];
__device__ float g_att  [Bb*Nn];
__device__ float g_part [Bb*20*Dd];

// ---------------- fp16 mma helpers ------------------------------------------
__device__ __forceinline__ uint32_t packh2(float x, float y) {
    __half2 h = __floats2half2_rn(x, y);
    return *(uint32_t*)&h;
}
__device__ __forceinline__ void mma_f16(float* c, const uint32_t* a, const uint32_t* b) {
    asm volatile("mma.sync.aligned.m16n8k16.row.col.f32.f16.f16.f32 "
                 "{%0,%1,%2,%3},{%4,%5,%6,%7},{%8,%9},{%0,%1,%2,%3};"
                 : "+f"(c[0]), "+f"(c[1]), "+f"(c[2]), "+f"(c[3])
                 : "r"(a[0]), "r"(a[1]), "r"(a[2]), "r"(a[3]),
                   "r"(b[0]), "r"(b[1]));
}
__device__ __forceinline__ uint32_t smem_u32(const void* p) {
    uint32_t a;
    asm("{ .reg .u64 t; cvta.to.shared.u64 t, %1; cvt.u32.u64 %0, t; }" : "=r"(a) : "l"(p));
    return a;
}
#define LDSM4(r0, r1, r2, r3, addr) \
    asm volatile("ldmatrix.sync.aligned.m8n8.x4.shared.b16 {%0,%1,%2,%3}, [%4];" \
                 : "=r"(r0), "=r"(r1), "=r"(r2), "=r"(r3) : "r"(addr))

#define LDW 20   // smem row stride in words

// ---------------- fp16 HMMA GEMM (R12 engine + R7-proven ldmatrix) -----------
template<int EPI, bool SPLITA, bool TRANSB>
__global__ __launch_bounds__(512)
void gemm_h(const float* __restrict__ A, const float* __restrict__ A2, int lda, long long sA,
            const float* __restrict__ Bm, int ldb, long long sB,
            const float* __restrict__ bias, const float* __restrict__ bias2,
            float* __restrict__ C, long long sC,
            float* __restrict__ C2,
            const float* __restrict__ aux1, const float* __restrict__ aux2,
            const float* __restrict__ rAv, float* __restrict__ rAout,
            int Klen)
{
    __shared__ __align__(16) uint32_t As[2][128 * LDW];
    __shared__ __align__(16) uint32_t Bs[2][128 * LDW];
    __shared__ float attp[4][132];

    const int tid  = threadIdx.x;
    const int warp = tid >> 5, lane = tid & 31;
    const int wm = warp & 3, wn = warp >> 2;
    const int group = lane >> 2, tig = lane & 3;

    const bool doAtt = (EPI == 7) && (blockIdx.y < 128);
    const int  n0g  = (EPI == 3) ? blockIdx.x * 128 : 0;
    const int  m0   = (EPI == 7) ? ((blockIdx.y & 127) * 128) : (blockIdx.y * 128);
    const long long bz = blockIdx.z;
    A  += bz * sA;
    Bm += bz * sB;
    C  += bz * sC;
    if (EPI == 7 && !doAtt) Bm = aux2;

    const int ar = tid >> 2, ak2 = (tid & 3) * 4;
    const int tk2 = tid & 15, tnb = (tid >> 4) * 4;

    // ldmatrix per-warp addresses (R7-proven mapping)
    const uint32_t aBase = smem_u32(&As[0][0]);
    const uint32_t bBase = smem_u32(&Bs[0][0]);
    const uint32_t BUFB  = 128 * LDW * 4;
    const int rowA = wm * 32 + (lane & 7) + ((lane >> 3) & 1) * 8;
    const uint32_t addrA0 = aBase + (uint32_t)((rowA * LDW + ((lane >> 4) & 1) * 4) * 4);
    const int rowB = wn * 32 + (lane & 7) + ((lane >> 4) & 1) * 8;
    const uint32_t addrB0 = bBase + (uint32_t)((rowB * LDW + ((lane >> 3) & 1) * 4) * 4);

    float acc[2][4][4];
#pragma unroll
    for (int i = 0; i < 2; i++)
#pragma unroll
        for (int j = 0; j < 4; j++)
#pragma unroll
            for (int q = 0; q < 4; q++) acc[i][j][q] = 0.f;

    float4 a0, a1, b0, b1;

    auto loadRegs = [&](int it) {
        const int k0 = it * 32;
        const float* asrc = (SPLITA && it * 32 >= 128)
            ? (A2 + (size_t)(m0 + ar) * 128 + (it * 32 - 128) + ak2 * 2)
            : (A  + (size_t)(m0 + ar) * lda + k0 + ak2 * 2);
        a0 = *(const float4*)asrc;
        a1 = *(const float4*)(asrc + 4);
        if (!TRANSB) {
            const float* bsrc = Bm + (size_t)(n0g + ar) * ldb + k0 + ak2 * 2;
            b0 = *(const float4*)bsrc;
            b1 = *(const float4*)(bsrc + 4);
        } else {
            const float* bsrc = Bm + (size_t)(k0 + 2 * tk2) * ldb + tnb;
            b0 = *(const float4*)bsrc;
            b1 = *(const float4*)(bsrc + ldb);
        }
    };

    auto stage = [&](int buf) {
        uint4 aw = { packh2(a0.x, a0.y), packh2(a0.z, a0.w),
                     packh2(a1.x, a1.y), packh2(a1.z, a1.w) };
        *(uint4*)&As[buf][ar * LDW + ak2] = aw;
        if (!TRANSB) {
            uint4 bw = { packh2(b0.x, b0.y), packh2(b0.z, b0.w),
                         packh2(b1.x, b1.y), packh2(b1.z, b1.w) };
            *(uint4*)&Bs[buf][ar * LDW + ak2] = bw;
        } else {
            Bs[buf][(tnb + 0) * LDW + tk2] = packh2(b0.x, b1.x);
            Bs[buf][(tnb + 1) * LDW + tk2] = packh2(b0.y, b1.y);
            Bs[buf][(tnb + 2) * LDW + tk2] = packh2(b0.z, b1.z);
            Bs[buf][(tnb + 3) * LDW + tk2] = packh2(b0.w, b1.w);
        }
    };

    const int niter = Klen / 32;
    loadRegs(0);
    stage(0);
    __syncthreads();

    for (int it = 0; it < niter; it++) {
        const int buf = it & 1;
        if (it + 1 < niter) loadRegs(it + 1);

#pragma unroll
        for (int s = 0; s < 2; s++) {
            uint32_t af[2][4], bf[4][2];
            const uint32_t aAddr = addrA0 + buf * BUFB + s * 32;
            const uint32_t bAddr = addrB0 + buf * BUFB + s * 32;
            LDSM4(af[0][0], af[0][1], af[0][2], af[0][3], aAddr);
            LDSM4(af[1][0], af[1][1], af[1][2], af[1][3], aAddr + 16 * LDW * 4);
            LDSM4(bf[0][0], bf[0][1], bf[1][0], bf[1][1], bAddr);
            LDSM4(bf[2][0], bf[2][1], bf[3][0], bf[3][1], bAddr + 16 * LDW * 4);
#pragma unroll
            for (int mi = 0; mi < 2; mi++)
#pragma unroll
                for (int ni = 0; ni < 4; ni++)
                    mma_f16(acc[mi][ni], af[mi], bf[ni]);
        }

        if (it + 1 < niter) stage((it + 1) & 1);
        __syncthreads();
    }

    if (EPI == 7 && doAtt) {
        float p[4] = {0.f, 0.f, 0.f, 0.f};
#pragma unroll
        for (int mi = 0; mi < 2; mi++)
#pragma unroll
            for (int ni = 0; ni < 4; ni++) {
                const int cl = wn * 32 + ni * 8 + 2 * tig;
#pragma unroll
                for (int rr = 0; rr < 2; rr++)
#pragma unroll
                    for (int cc = 0; cc < 2; cc++) {
                        const int col = cl + cc;
                        const float v = tanhf(acc[mi][ni][rr * 2 + cc] + bias[col]);
                        p[mi * 2 + rr] += v * aux1[col];
                    }
            }
#pragma unroll
        for (int i = 0; i < 4; i++) {
            p[i] += __shfl_xor_sync(0xffffffffu, p[i], 1);
            p[i] += __shfl_xor_sync(0xffffffffu, p[i], 2);
        }
        if (tig == 0) {
#pragma unroll
            for (int mi = 0; mi < 2; mi++)
#pragma unroll
                for (int rr = 0; rr < 2; rr++)
                    attp[wn][wm * 32 + mi * 16 + group + rr * 8] = p[mi * 2 + rr];
        }
        __syncthreads();
        if (tid < 128)
            C[m0 + tid] = ((attp[0][tid] + attp[1][tid]) +
                           (attp[2][tid] + attp[3][tid])) + bias2[0];
        return;
    }

#pragma unroll
    for (int mi = 0; mi < 2; mi++) {
#pragma unroll
        for (int ni = 0; ni < 4; ni++) {
            const int cl = wn * 32 + ni * 8 + 2 * tig;
#pragma unroll
            for (int rr = 0; rr < 2; rr++) {
                const long long r = m0 + wm * 32 + mi * 16 + group + rr * 8;
#pragma unroll
                for (int cc = 0; cc < 2; cc++) {
                    float v = acc[mi][ni][rr * 2 + cc];
                    const int col  = cl + cc;
                    const int gcol = n0g + col;
                    if (EPI == 1) {
                        C[r * 128 + col] = v + bias[col];
                    } else if (EPI == 3) {
                        v = 1.f / (1.f + __expf(-(v + rAv[r] * bias[gcol] + bias2[gcol])));
                        if (blockIdx.x == 0) C2[r * 128 + col] = v * aux2[r * 128 + col];
                        else                 C [r * 128 + col] = v;
                    } else if (EPI == 4) {
                        const float h = tanhf(v + rAv[r] * bias[col] + bias2[col]);
                        const float z = aux1[r * 128 + col];
                        const float p = aux2[r * 128 + col];
                        C[r * 128 + col] = fmaf(z, h - p, p);
                    } else if (EPI == 7) {
                        C2[r * 128 + col] = tanhf(v + rAv[col]);
                    }
                }
            }
        }
    }
}

// ---------------- R6-proven fold body as device function ---------------------
__device__ void fold_dev(int x, int y, int tid,
                         const float* __restrict__ W1, const float* __restrict__ W2,
                         const float* __restrict__ W3,
                         const float* __restrict__ rW, const float* __restrict__ uW,
                         const float* __restrict__ rb, const float* __restrict__ ub,
                         const float* __restrict__ tW,
                         const float* __restrict__ attW1, const float* __restrict__ outW,
                         const float* __restrict__ cvec,
                         float* __restrict__ WrzTs, float* __restrict__ TTs,
                         float* __restrict__ W3T, float* __restrict__ attW1T,
                         float* __restrict__ outWT,
                         float* __restrict__ betarz, float* __restrict__ betah,
                         float* __restrict__ brz) {
    const float* Wpow[3] = { W1, W2, W3 };

    auto wrz = [&](int j, int n) -> float {
        return (n < 128) ? rW[j * 128 + n] : uW[j * 128 + (n - 128)];
    };

    if (y < 3) {
        const float* Ws = Wpow[y];
        float s = 0.f;
#pragma unroll 4
        for (int j = 0; j < 128; j++) s = fmaf(Ws[x * 128 + j], wrz(j, tid), s);
        WrzTs[(size_t)y * 65536 + (size_t)tid * 256 + x] = s;
    } else if (y < 6) {
        WrzTs[(size_t)(y - 3) * 65536 + (size_t)tid * 256 + 128 + x] = wrz(128 + x, tid);
    } else if (y < 9) {
        if (tid < 128) {
            const float* Ws = Wpow[y - 6];
            float s = 0.f;
#pragma unroll 4
            for (int j = 0; j < 128; j++) s = fmaf(Ws[x * 128 + j], tW[j * 128 + tid], s);
            TTs[(size_t)(y - 6) * 32768 + (size_t)tid * 256 + x] = s;
        }
    } else if (y < 12) {
        if (tid < 128)
            TTs[(size_t)(y - 9) * 32768 + (size_t)tid * 256 + 128 + x] = tW[(128 + x) * 128 + tid];
    } else if (y == 12) {
        if (tid < 128) W3T[tid * 128 + x] = W3[x * 128 + tid];
    } else if (y == 13) {
        if (tid < 128) attW1T[tid * 128 + x] = attW1[x * 128 + tid];
    } else if (y == 14) {
        if (tid < 128) outWT[tid * 128 + x] = outW[x * 128 + tid];
    } else {
        if (x < 3) {
            const float* c = cvec + x * 128;
            float s = 0.f;
#pragma unroll 4
            for (int j = 0; j < 128; j++) s = fmaf(c[j], wrz(j, tid), s);
            betarz[x * 256 + tid] = s;
            if (tid < 128) {
                float h = 0.f;
#pragma unroll 4
                for (int j = 0; j < 128; j++) h = fmaf(c[j], tW[j * 128 + tid], h);
                betah[x * 128 + tid] = h;
            }
        } else if (x == 3) {
            brz[tid] = (tid < 128) ? rb[tid] : ub[tid - 128];
        }
    }
}

// Full-chip fold launch (R6-proven shape): grid (128,16), block 256.
__global__ void k_fold(const float* __restrict__ W1, const float* __restrict__ W2,
                       const float* __restrict__ W3,
                       const float* __restrict__ rW, const float* __restrict__ uW,
                       const float* __restrict__ rb, const float* __restrict__ ub,
                       const float* __restrict__ tW,
                       const float* __restrict__ attW1, const float* __restrict__ outW,
                       const float* __restrict__ cvec,
                       float* __restrict__ WrzTs, float* __restrict__ TTs,
                       float* __restrict__ W3T, float* __restrict__ attW1T,
                       float* __restrict__ outWT,
                       float* __restrict__ betarz, float* __restrict__ betah,
                       float* __restrict__ brz) {
    fold_dev(blockIdx.x, blockIdx.y, threadIdx.x,
             W1, W2, W3, rW, uW, rb, ub, tW, attW1, outW, cvec,
             WrzTs, TTs, W3T, attW1T, outWT, betarz, betah, brz);
}

// ---------------- MEGA kernel: 148 CTAs, single wave -------------------------
//   bid 0..127  : G0 GEMM (ldmatrix fragments) + rowsum(A)
//   bid 128..147: residual-only riders (8 chunks each, inside GEMM shadow)
__global__ __launch_bounds__(512)
void k_mega(const float* __restrict__ Amat, const float* __restrict__ edge_in,
            const float* __restrict__ prop_in,
            float* __restrict__ G0, float* __restrict__ rAout,
            float* __restrict__ part)
{
    __shared__ __align__(16) uint32_t As[2][128 * LDW];
    __shared__ __align__(16) uint32_t Bs[2][128 * LDW];

    const int bid = blockIdx.x;
    const int tid = threadIdx.x;

    if (bid >= 128) {
        const int rc = bid - 128;        // 0..19
        for (int k = 0; k < 8; k++) {
            const int rid = rc + 20 * k;
            const int b  = rid / 5;
            const int ch = (rid % 5) * 4 + (tid >> 7);
            const int d  = tid & 127;
            float s = 0.f;
            const int r0 = ch * 128;
#pragma unroll 4
            for (int r = r0; r < r0 + 128; r++) {
                if (r < Nn) s += prop_in[((long long)b * Nn + r) * Dd + d];
                else        s += edge_in[((long long)b * Ee + (r - Nn)) * Dd + d];
            }
            part[(b * 20 + ch) * Dd + d] = s;
        }
        return;
    }

    // ---- G0 GEMM CTA ----
    const int warp = tid >> 5, lane = tid & 31;
    const int wm = warp & 3, wn = warp >> 2;
    const int group = lane >> 2, tig = lane & 3;
    const int m0 = (bid & 3) * 128;
    const long long bz = bid >> 2;
    const float* A  = Amat    + bz * (long long)Nn * Ee;
    const float* Bm = edge_in + bz * (long long)Ee * Dd;
    float* C = G0 + bz * (long long)Nn * 128;

    const int ar = tid >> 2, ak2 = (tid & 3) * 4;
    const int tk2 = tid & 15, tnb = (tid >> 4) * 4;

    const uint32_t aBase = smem_u32(&As[0][0]);
    const uint32_t bBase = smem_u32(&Bs[0][0]);
    const uint32_t BUFB  = 128 * LDW * 4;
    const int rowA = wm * 32 + (lane & 7) + ((lane >> 3) & 1) * 8;
    const uint32_t addrA0 = aBase + (uint32_t)((rowA * LDW + ((lane >> 4) & 1) * 4) * 4);
    const int rowB = wn * 32 + (lane & 7) + ((lane >> 4) & 1) * 8;
    const uint32_t addrB0 = bBase + (uint32_t)((rowB * LDW + ((lane >> 3) & 1) * 4) * 4);

    float acc[2][4][4];
#pragma unroll
    for (int i = 0; i < 2; i++)
#pragma unroll
        for (int j = 0; j < 4; j++)
#pragma unroll
            for (int q = 0; q < 4; q++) acc[i][j][q] = 0.f;

    float rsum = 0.f;
    float4 a0, a1, b0, b1;

    auto loadRegs = [&](int it) {
        const int k0 = it * 32;
        const float* asrc = A + (size_t)(m0 + ar) * Ee + k0 + ak2 * 2;
        a0 = *(const float4*)asrc;
        a1 = *(const float4*)(asrc + 4);
        rsum += ((a0.x + a0.y) + (a0.z + a0.w)) + ((a1.x + a1.y) + (a1.z + a1.w));
        const float* bsrc = Bm + (size_t)(k0 + 2 * tk2) * Dd + tnb;
        b0 = *(const float4*)bsrc;
        b1 = *(const float4*)(bsrc + Dd);
    };

    auto stage = [&](int buf) {
        uint4 aw = { packh2(a0.x, a0.y), packh2(a0.z, a0.w),
                     packh2(a1.x, a1.y), packh2(a1.z, a1.w) };
        *(uint4*)&As[buf][ar * LDW + ak2] = aw;
        Bs[buf][(tnb + 0) * LDW + tk2] = packh2(b0.x, b1.x);
        Bs[buf][(tnb + 1) * LDW + tk2] = packh2(b0.y, b1.y);
        Bs[buf][(tnb + 2) * LDW + tk2] = packh2(b0.z, b1.z);
        Bs[buf][(tnb + 3) * LDW + tk2] = packh2(b0.w, b1.w);
    };

    const int niter = Ee / 32;
    loadRegs(0);
    stage(0);
    __syncthreads();

    for (int it = 0; it < niter; it++) {
        const int buf = it & 1;
        if (it + 1 < niter) loadRegs(it + 1);

#pragma unroll
        for (int s = 0; s < 2; s++) {
            uint32_t af[2][4], bf[4][2];
            const uint32_t aAddr = addrA0 + buf * BUFB + s * 32;
            const uint32_t bAddr = addrB0 + buf * BUFB + s * 32;
            LDSM4(af[0][0], af[0][1], af[0][2], af[0][3], aAddr);
            LDSM4(af[1][0], af[1][1], af[1][2], af[1][3], aAddr + 16 * LDW * 4);
            LDSM4(bf[0][0], bf[0][1], bf[1][0], bf[1][1], bAddr);
            LDSM4(bf[2][0], bf[2][1], bf[3][0], bf[3][1], bAddr + 16 * LDW * 4);
#pragma unroll
            for (int mi = 0; mi < 2; mi++)
#pragma unroll
                for (int ni = 0; ni < 4; ni++)
                    mma_f16(acc[mi][ni], af[mi], bf[ni]);
        }

        if (it + 1 < niter) stage((it + 1) & 1);
        __syncthreads();
    }

    {
        float s = rsum;
        s += __shfl_xor_sync(0xffffffffu, s, 1);
        s += __shfl_xor_sync(0xffffffffu, s, 2);
        if ((tid & 3) == 0)
            rAout[bz * Nn + m0 + ar] = s;
    }

#pragma unroll
    for (int mi = 0; mi < 2; mi++) {
#pragma unroll
        for (int ni = 0; ni < 4; ni++) {
            const int cl = wn * 32 + ni * 8 + 2 * tig;
#pragma unroll
            for (int rr = 0; rr < 2; rr++) {
                const long long r = m0 + wm * 32 + mi * 16 + group + rr * 8;
#pragma unroll
                for (int cc = 0; cc < 2; cc++)
                    C[r * 128 + cl + cc] = acc[mi][ni][rr * 2 + cc];
            }
        }
    }
}

// ---------------- prep kernels ------------------------------------------------
__global__ void k_mm128(const float* __restrict__ A, const float* __restrict__ B,
                        float* __restrict__ C) {
    const int r = blockIdx.x, c = threadIdx.x;
    __shared__ float sA[128];
    sA[c] = A[r * 128 + c];
    __syncthreads();
    float s0 = 0.f, s1 = 0.f, s2 = 0.f, s3 = 0.f;
#pragma unroll
    for (int k = 0; k < 128; k += 4) {
        s0 = fmaf(sA[k + 0], B[(k + 0) * 128 + c], s0);
        s1 = fmaf(sA[k + 1], B[(k + 1) * 128 + c], s1);
        s2 = fmaf(sA[k + 2], B[(k + 2) * 128 + c], s2);
        s3 = fmaf(sA[k + 3], B[(k + 3) * 128 + c], s3);
    }
    C[r * 128 + c] = (s0 + s1) + (s2 + s3);
}

__global__ void k_cvec(const float* __restrict__ b, const float* __restrict__ W,
                       const float* __restrict__ W2, float* __restrict__ c) {
    const int col  = blockIdx.x * 8 + (threadIdx.x >> 5);
    const int lane = threadIdx.x & 31;
    float sw = 0.f, sw2 = 0.f;
#pragma unroll
    for (int k = lane; k < 128; k += 32) {
        const float bk = b[k];
        sw  = fmaf(bk, W [k * 128 + col], sw);
        sw2 = fmaf(bk, W2[k * 128 + col], sw2);
    }
#pragma unroll
    for (int o = 16; o; o >>= 1) {
        sw  += __shfl_xor_sync(0xffffffffu, sw, o);
        sw2 += __shfl_xor_sync(0xffffffffu, sw2, o);
    }
    if (lane == 0) {
        const float bc = b[col];
        c[col]       = bc;
        c[128 + col] = bc + sw;
        c[256 + col] = bc + sw + sw2;
    }
}

// ---------------- misc kernels -------------------------------------------------
__global__ void k_final(const float* __restrict__ att, const float* __restrict__ outn,
                        const float* __restrict__ part,
                        float* __restrict__ d_res, float* __restrict__ d_mul) {
    const int b = blockIdx.x, d = threadIdx.x;
    __shared__ float sa[Nn];
    __shared__ float red[128];
    float lm = -1e30f;
#pragma unroll
    for (int i = 0; i < 4; i++) {
        const float v = att[b * Nn + d + i * 128];
        sa[d + i * 128] = v;
        lm = fmaxf(lm, v);
    }
    red[d] = lm;
    __syncthreads();
    for (int s = 64; s; s >>= 1) { if (d < s) red[d] = fmaxf(red[d], red[d + s]); __syncthreads(); }
    const float M = red[0];
    __syncthreads();
    float ls = 0.f;
#pragma unroll
    for (int i = 0; i < 4; i++) {
        const float e = __expf(sa[d + i * 128] - M);
        sa[d + i * 128] = e;
        ls += e;
    }
    red[d] = ls;
    __syncthreads();
    for (int s = 64; s; s >>= 1) { if (d < s) red[d] += red[d + s]; __syncthreads(); }
    const float S = red[0];
    __syncthreads();

    const float* ob = outn + (long long)b * Nn * Dd;
    float acc = 0.f;
#pragma unroll 8
    for (int n = 0; n < Nn; n++) acc = fmaf(sa[n], ob[n * Dd + d], acc);
    acc /= S;
    float resid = 0.f;
#pragma unroll
    for (int c = 0; c < 20; c++) resid += part[(b * 20 + c) * Dd + d];
    resid *= (1.f / 2560.f);
    d_mul[b * Dd + d] = acc;
    d_res[b * Dd + d] = fmaxf(tanhf(acc) + resid, 0.f);
}

// ---------------- host launch ----------------------------------------------------
static float* sym(const void* s) { void* p = nullptr; cudaGetSymbolAddress(&p, s); return (float*)p; }

extern "C" void kernel_launch(void* const* d_in, const int* in_sizes, int n_in,
                              void* d_out, int out_size) {
    const float* prop_in = (const float*)d_in[0];
    const float* edge_in = (const float*)d_in[1];
    const float* Amat    = (const float*)d_in[2];
    const float* link_W  = (const float*)d_in[4];
    const float* link_b  = (const float*)d_in[5];
    const float* reset_W = (const float*)d_in[6];
    const float* reset_b = (const float*)d_in[7];
    const float* upd_W   = (const float*)d_in[8];
    const float* upd_b   = (const float*)d_in[9];
    const float* trans_W = (const float*)d_in[10];
    const float* trans_b = (const float*)d_in[11];
    const float* att_W1  = (const float*)d_in[12];
    const float* att_b1  = (const float*)d_in[13];
    const float* att_W2  = (const float*)d_in[14];
    const float* att_b2  = (const float*)d_in[15];
    const float* out_W   = (const float*)d_in[16];
    const float* out_b   = (const float*)d_in[17];

    float* out      = (float*)d_out;
    float* out_res  = out;
    float* out_mul  = out + Bb * Dd;
    float* out_edge = out + 2 * Bb * Dd;

    float* G0 = sym(g_G0); float* prop = sym(g_prop); float* rp = sym(g_rp);
    float* zbuf = sym(g_zbuf); float* outn = sym(g_outn); float* rA = sym(g_rA);
    float* WrzTs = sym(g_WrzTs); float* TTs = sym(g_TTs);
    float* betarz = sym(g_betarz); float* betah = sym(g_betah); float* brz = sym(g_brz);
    float* attW1T = sym(g_attW1T); float* outWT = sym(g_outWT);
    float* W2 = sym(g_W2); float* W3 = sym(g_W3); float* W3T = sym(g_W3T);
    float* cvec = sym(g_c);
    float* att = sym(g_att); float* part = sym(g_part);

    // --- tiny serial prep (fold inputs) ---
    k_mm128<<<128, 128>>>(link_W, link_W, W2);
    k_mm128<<<128, 128>>>(W2, link_W, W3);
    k_cvec<<<16, 256>>>(link_b, link_W, W2, cvec);

    // --- MEGA: 148 CTAs, one wave. G0 GEMM (ldmatrix) + residual riders ---
    k_mega<<<148, 512>>>(Amat, edge_in, prop_in, G0, rA, part);

    // --- fold: full-chip launch ---
    k_fold<<<dim3(128, 16), 256>>>(link_W, W2, W3, reset_W, upd_W, reset_b, upd_b,
                                   trans_W, att_W1, out_W, cvec,
                                   WrzTs, TTs, W3T, attW1T, outWT,
                                   betarz, betah, brz);

    // edge_states output: e3 = e0 @ W3 + c3
    gemm_h<1, false, false><<<dim3(1, (Bb * Ee) / 128, 1), 512>>>(
        edge_in, nullptr, 128, 0, W3T, 128, 0, cvec + 256, nullptr,
        out_edge, 0, nullptr, nullptr, nullptr, nullptr, nullptr, 128);

    // --- 3 GRU steps ---
    const float* prop_cur = prop_in;
    for (int s = 0; s < NSTEP; s++) {
        gemm_h<3, true, false><<<dim3(2, MROWS / 128, 1), 512>>>(
            G0, prop_cur, 128, 0, WrzTs + (size_t)s * 65536, 256, 0,
            betarz + s * 256, brz,
            zbuf, 0, rp, nullptr, prop_cur, rA, nullptr, 256);
        gemm_h<4, true, false><<<dim3(1, MROWS / 128, 1), 512>>>(
            G0, rp, 128, 0, TTs + (size_t)s * 32768, 256, 0,
            betah + s * 128, trans_b,
            prop, 0, nullptr, zbuf, prop_cur, rA, nullptr, 256);
        prop_cur = prop;
    }

    // --- merged epilogue GEMM: by<128 att score, by>=128 outn ---
    gemm_h<7, false, false><<<dim3(1, 256, 1), 512>>>(
        prop, nullptr, 128, 0, attW1T, 128, 0, att_b1, att_b2,
        att, 0, outn, att_W2, outWT, out_b, nullptr, 128);

    k_final<<<Bb, Dd>>>(att, outn, part, out_res, out_mul);
}

// round 17
// speedup vs baseline: 1.2447x; 1.0120x over previous
#include <cuda_runtime.h>
#include <cuda_fp16.h>
#include <math.h>
#include <stdint.h>

#define Bb 32
#define Nn 512
#define Ee 2048
#define Dd 128
#define NSTEP 3
#define MROWS (Bb*Nn)          // 16384

// ---------------- scratch (device globals: allocation-free) ----------------
__device__ float g_G0   [MROWS*Dd];
__device__ float g_prop [MROWS*Dd];
__device__ float g_rp   [MROWS*Dd];
__device__ float g_zbuf [MROWS*Dd];
__device__ float g_outn [MROWS*Dd];
__device__ float g_rA   [MROWS];
__device__ float g_WrzTs[3*256*256];    // per-step folded [N=256][K=256]
__device__ float g_TTs  [3*Dd*256];     // per-step folded [N=128][K=256]
__device__ float g_betarz[3*256];
__device__ float g_betah [3*Dd];
__device__ float g_brz  [256];
__device__ float g_attW1T[Dd*Dd];
__device__ float g_outWT [Dd*Dd];
__device__ float g_W2   [Dd*Dd];
__device__ float g_W3   [Dd*Dd];
__device__ float g_W3T  [Dd*Dd];
__device__ float g_c    [3*Dd];
__device__ float g_att  [Bb*Nn];
__device__ float g_part [Bb*20*Dd];

// ---------------- fp16 mma helpers ------------------------------------------
__device__ __forceinline__ uint32_t packh2(float x, float y) {
    __half2 h = __floats2half2_rn(x, y);
    return *(uint32_t*)&h;
}
__device__ __forceinline__ void mma_f16(float* c, const uint32_t* a, const uint32_t* b) {
    asm volatile("mma.sync.aligned.m16n8k16.row.col.f32.f16.f16.f32 "
                 "{%0,%1,%2,%3},{%4,%5,%6,%7},{%8,%9},{%0,%1,%2,%3};"
                 : "+f"(c[0]), "+f"(c[1]), "+f"(c[2]), "+f"(c[3])
                 : "r"(a[0]), "r"(a[1]), "r"(a[2]), "r"(a[3]),
                   "r"(b[0]), "r"(b[1]));
}
__device__ __forceinline__ uint32_t smem_u32(const void* p) {
    uint32_t a;
    asm("{ .reg .u64 t; cvta.to.shared.u64 t, %1; cvt.u32.u64 %0, t; }" : "=r"(a) : "l"(p));
    return a;
}
#define LDSM4(r0, r1, r2, r3, addr) \
    asm volatile("ldmatrix.sync.aligned.m8n8.x4.shared.b16 {%0,%1,%2,%3}, [%4];" \
                 : "=r"(r0), "=r"(r1), "=r"(r2), "=r"(r3) : "r"(addr))

#define LDW 20   // smem row stride in words

// ---------------- fp16 HMMA GEMM (R16-proven engine; EPI 3/4/7) --------------
template<int EPI, bool SPLITA, bool TRANSB>
__global__ __launch_bounds__(512)
void gemm_h(const float* __restrict__ A, const float* __restrict__ A2, int lda, long long sA,
            const float* __restrict__ Bm, int ldb, long long sB,
            const float* __restrict__ bias, const float* __restrict__ bias2,
            float* __restrict__ C, long long sC,
            float* __restrict__ C2,
            const float* __restrict__ aux1, const float* __restrict__ aux2,
            const float* __restrict__ rAv, float* __restrict__ rAout,
            int Klen)
{
    __shared__ __align__(16) uint32_t As[2][128 * LDW];
    __shared__ __align__(16) uint32_t Bs[2][128 * LDW];
    __shared__ float attp[4][132];

    const int tid  = threadIdx.x;
    const int warp = tid >> 5, lane = tid & 31;
    const int wm = warp & 3, wn = warp >> 2;
    const int group = lane >> 2, tig = lane & 3;

    const bool doAtt = (EPI == 7) && (blockIdx.y < 128);
    const int  n0g  = (EPI == 3) ? blockIdx.x * 128 : 0;
    const int  m0   = (EPI == 7) ? ((blockIdx.y & 127) * 128) : (blockIdx.y * 128);
    const long long bz = blockIdx.z;
    A  += bz * sA;
    Bm += bz * sB;
    C  += bz * sC;
    if (EPI == 7 && !doAtt) Bm = aux2;

    const int ar = tid >> 2, ak2 = (tid & 3) * 4;
    const int tk2 = tid & 15, tnb = (tid >> 4) * 4;

    const uint32_t aBase = smem_u32(&As[0][0]);
    const uint32_t bBase = smem_u32(&Bs[0][0]);
    const uint32_t BUFB  = 128 * LDW * 4;
    const int rowA = wm * 32 + (lane & 7) + ((lane >> 3) & 1) * 8;
    const uint32_t addrA0 = aBase + (uint32_t)((rowA * LDW + ((lane >> 4) & 1) * 4) * 4);
    const int rowB = wn * 32 + (lane & 7) + ((lane >> 4) & 1) * 8;
    const uint32_t addrB0 = bBase + (uint32_t)((rowB * LDW + ((lane >> 3) & 1) * 4) * 4);

    float acc[2][4][4];
#pragma unroll
    for (int i = 0; i < 2; i++)
#pragma unroll
        for (int j = 0; j < 4; j++)
#pragma unroll
            for (int q = 0; q < 4; q++) acc[i][j][q] = 0.f;

    float4 a0, a1, b0, b1;

    auto loadRegs = [&](int it) {
        const int k0 = it * 32;
        const float* asrc = (SPLITA && it * 32 >= 128)
            ? (A2 + (size_t)(m0 + ar) * 128 + (it * 32 - 128) + ak2 * 2)
            : (A  + (size_t)(m0 + ar) * lda + k0 + ak2 * 2);
        a0 = *(const float4*)asrc;
        a1 = *(const float4*)(asrc + 4);
        if (!TRANSB) {
            const float* bsrc = Bm + (size_t)(n0g + ar) * ldb + k0 + ak2 * 2;
            b0 = *(const float4*)bsrc;
            b1 = *(const float4*)(bsrc + 4);
        } else {
            const float* bsrc = Bm + (size_t)(k0 + 2 * tk2) * ldb + tnb;
            b0 = *(const float4*)bsrc;
            b1 = *(const float4*)(bsrc + ldb);
        }
    };

    auto stage = [&](int buf) {
        uint4 aw = { packh2(a0.x, a0.y), packh2(a0.z, a0.w),
                     packh2(a1.x, a1.y), packh2(a1.z, a1.w) };
        *(uint4*)&As[buf][ar * LDW + ak2] = aw;
        if (!TRANSB) {
            uint4 bw = { packh2(b0.x, b0.y), packh2(b0.z, b0.w),
                         packh2(b1.x, b1.y), packh2(b1.z, b1.w) };
            *(uint4*)&Bs[buf][ar * LDW + ak2] = bw;
        } else {
            Bs[buf][(tnb + 0) * LDW + tk2] = packh2(b0.x, b1.x);
            Bs[buf][(tnb + 1) * LDW + tk2] = packh2(b0.y, b1.y);
            Bs[buf][(tnb + 2) * LDW + tk2] = packh2(b0.z, b1.z);
            Bs[buf][(tnb + 3) * LDW + tk2] = packh2(b0.w, b1.w);
        }
    };

    const int niter = Klen / 32;
    loadRegs(0);
    stage(0);
    __syncthreads();

    for (int it = 0; it < niter; it++) {
        const int buf = it & 1;
        if (it + 1 < niter) loadRegs(it + 1);

#pragma unroll
        for (int s = 0; s < 2; s++) {
            uint32_t af[2][4], bf[4][2];
            const uint32_t aAddr = addrA0 + buf * BUFB + s * 32;
            const uint32_t bAddr = addrB0 + buf * BUFB + s * 32;
            LDSM4(af[0][0], af[0][1], af[0][2], af[0][3], aAddr);
            LDSM4(af[1][0], af[1][1], af[1][2], af[1][3], aAddr + 16 * LDW * 4);
            LDSM4(bf[0][0], bf[0][1], bf[1][0], bf[1][1], bAddr);
            LDSM4(bf[2][0], bf[2][1], bf[3][0], bf[3][1], bAddr + 16 * LDW * 4);
#pragma unroll
            for (int mi = 0; mi < 2; mi++)
#pragma unroll
                for (int ni = 0; ni < 4; ni++)
                    mma_f16(acc[mi][ni], af[mi], bf[ni]);
        }

        if (it + 1 < niter) stage((it + 1) & 1);
        __syncthreads();
    }

    if (EPI == 7 && doAtt) {
        float p[4] = {0.f, 0.f, 0.f, 0.f};
#pragma unroll
        for (int mi = 0; mi < 2; mi++)
#pragma unroll
            for (int ni = 0; ni < 4; ni++) {
                const int cl = wn * 32 + ni * 8 + 2 * tig;
#pragma unroll
                for (int rr = 0; rr < 2; rr++)
#pragma unroll
                    for (int cc = 0; cc < 2; cc++) {
                        const int col = cl + cc;
                        const float v = tanhf(acc[mi][ni][rr * 2 + cc] + bias[col]);
                        p[mi * 2 + rr] += v * aux1[col];
                    }
            }
#pragma unroll
        for (int i = 0; i < 4; i++) {
            p[i] += __shfl_xor_sync(0xffffffffu, p[i], 1);
            p[i] += __shfl_xor_sync(0xffffffffu, p[i], 2);
        }
        if (tig == 0) {
#pragma unroll
            for (int mi = 0; mi < 2; mi++)
#pragma unroll
                for (int rr = 0; rr < 2; rr++)
                    attp[wn][wm * 32 + mi * 16 + group + rr * 8] = p[mi * 2 + rr];
        }
        __syncthreads();
        if (tid < 128)
            C[m0 + tid] = ((attp[0][tid] + attp[1][tid]) +
                           (attp[2][tid] + attp[3][tid])) + bias2[0];
        return;
    }

#pragma unroll
    for (int mi = 0; mi < 2; mi++) {
#pragma unroll
        for (int ni = 0; ni < 4; ni++) {
            const int cl = wn * 32 + ni * 8 + 2 * tig;
#pragma unroll
            for (int rr = 0; rr < 2; rr++) {
                const long long r = m0 + wm * 32 + mi * 16 + group + rr * 8;
#pragma unroll
                for (int cc = 0; cc < 2; cc++) {
                    float v = acc[mi][ni][rr * 2 + cc];
                    const int col  = cl + cc;
                    const int gcol = n0g + col;
                    if (EPI == 3) {
                        v = 1.f / (1.f + __expf(-(v + rAv[r] * bias[gcol] + bias2[gcol])));
                        if (blockIdx.x == 0) C2[r * 128 + col] = v * aux2[r * 128 + col];
                        else                 C [r * 128 + col] = v;
                    } else if (EPI == 4) {
                        const float h = tanhf(v + rAv[r] * bias[col] + bias2[col]);
                        const float z = aux1[r * 128 + col];
                        const float p = aux2[r * 128 + col];
                        C[r * 128 + col] = fmaf(z, h - p, p);
                    } else if (EPI == 7) {
                        C2[r * 128 + col] = tanhf(v + rAv[col]);
                    }
                }
            }
        }
    }
}

// ---------------- R6-proven fold body as device function ---------------------
__device__ void fold_dev(int x, int y, int tid,
                         const float* __restrict__ W1, const float* __restrict__ W2,
                         const float* __restrict__ W3,
                         const float* __restrict__ rW, const float* __restrict__ uW,
                         const float* __restrict__ rb, const float* __restrict__ ub,
                         const float* __restrict__ tW,
                         const float* __restrict__ attW1, const float* __restrict__ outW,
                         const float* __restrict__ cvec,
                         float* __restrict__ WrzTs, float* __restrict__ TTs,
                         float* __restrict__ W3T, float* __restrict__ attW1T,
                         float* __restrict__ outWT,
                         float* __restrict__ betarz, float* __restrict__ betah,
                         float* __restrict__ brz) {
    const float* Wpow[3] = { W1, W2, W3 };

    auto wrz = [&](int j, int n) -> float {
        return (n < 128) ? rW[j * 128 + n] : uW[j * 128 + (n - 128)];
    };

    if (y < 3) {
        const float* Ws = Wpow[y];
        float s = 0.f;
#pragma unroll 4
        for (int j = 0; j < 128; j++) s = fmaf(Ws[x * 128 + j], wrz(j, tid), s);
        WrzTs[(size_t)y * 65536 + (size_t)tid * 256 + x] = s;
    } else if (y < 6) {
        WrzTs[(size_t)(y - 3) * 65536 + (size_t)tid * 256 + 128 + x] = wrz(128 + x, tid);
    } else if (y < 9) {
        if (tid < 128) {
            const float* Ws = Wpow[y - 6];
            float s = 0.f;
#pragma unroll 4
            for (int j = 0; j < 128; j++) s = fmaf(Ws[x * 128 + j], tW[j * 128 + tid], s);
            TTs[(size_t)(y - 6) * 32768 + (size_t)tid * 256 + x] = s;
        }
    } else if (y < 12) {
        if (tid < 128)
            TTs[(size_t)(y - 9) * 32768 + (size_t)tid * 256 + 128 + x] = tW[(128 + x) * 128 + tid];
    } else if (y == 12) {
        if (tid < 128) W3T[tid * 128 + x] = W3[x * 128 + tid];
    } else if (y == 13) {
        if (tid < 128) attW1T[tid * 128 + x] = attW1[x * 128 + tid];
    } else if (y == 14) {
        if (tid < 128) outWT[tid * 128 + x] = outW[x * 128 + tid];
    } else {
        if (x < 3) {
            const float* c = cvec + x * 128;
            float s = 0.f;
#pragma unroll 4
            for (int j = 0; j < 128; j++) s = fmaf(c[j], wrz(j, tid), s);
            betarz[x * 256 + tid] = s;
            if (tid < 128) {
                float h = 0.f;
#pragma unroll 4
                for (int j = 0; j < 128; j++) h = fmaf(c[j], tW[j * 128 + tid], h);
                betah[x * 128 + tid] = h;
            }
        } else if (x == 3) {
            brz[tid] = (tid < 128) ? rb[tid] : ub[tid - 128];
        }
    }
}

// ---------------- MEGA kernel: G0 + residual + e3 + fold, one launch ---------
//   bid 0..127   : G0 GEMM (m-tile = bid&3, batch = bid>>2) + rowsum(A)
//   bid 128..147 : residual riders (wave-1 on the 20 idle SMs)
//   bid 148..659 : e3 GEMM tiles (fill shadow + tail):
//                  out_edge[t*128.., :] = edge@W3 + c3  (A=edge flat, B=W3 TRANSB)
//   bid 660..1683: fold units (2 per CTA, R10-proven dispatch)
__global__ __launch_bounds__(512)
void k_mega(const float* __restrict__ Amat, const float* __restrict__ edge_in,
            const float* __restrict__ prop_in,
            const float* __restrict__ W3v, const float* __restrict__ cvec,
            const float* __restrict__ W1, const float* __restrict__ W2,
            const float* __restrict__ rW, const float* __restrict__ uW,
            const float* __restrict__ rb, const float* __restrict__ ub,
            const float* __restrict__ tW,
            const float* __restrict__ attW1, const float* __restrict__ outW,
            float* __restrict__ WrzTs, float* __restrict__ TTs,
            float* __restrict__ W3T, float* __restrict__ attW1T,
            float* __restrict__ outWT,
            float* __restrict__ betarz, float* __restrict__ betah,
            float* __restrict__ brz,
            float* __restrict__ G0, float* __restrict__ rAout,
            float* __restrict__ part, float* __restrict__ out_edge)
{
    const int bid = blockIdx.x;
    const int tid = threadIdx.x;

    if (bid >= 128 && bid < 148) {           // residual riders
        const int rc = bid - 128;
        for (int k = 0; k < 8; k++) {
            const int rid = rc + 20 * k;
            const int b  = rid / 5;
            const int ch = (rid % 5) * 4 + (tid >> 7);
            const int d  = tid & 127;
            float s = 0.f;
            const int r0 = ch * 128;
#pragma unroll 4
            for (int r = r0; r < r0 + 128; r++) {
                if (r < Nn) s += prop_in[((long long)b * Nn + r) * Dd + d];
                else        s += edge_in[((long long)b * Ee + (r - Nn)) * Dd + d];
            }
            part[(b * 20 + ch) * Dd + d] = s;
        }
        return;
    }
    if (bid >= 660) {                        // fold units (2 per CTA)
        const int fid = (bid - 660) * 2 + (tid >> 8);
        fold_dev(fid & 127, fid >> 7, tid & 255,
                 W1, W2, W3v, rW, uW, rb, ub, tW, attW1, outW, cvec,
                 WrzTs, TTs, W3T, attW1T, outWT, betarz, betah, brz);
        return;
    }

    // ---- GEMM CTA: role G0 (bid<128) or e3 (148<=bid<660). B is TRANSB. ----
    __shared__ __align__(16) uint32_t As[2][128 * LDW];
    __shared__ __align__(16) uint32_t Bs[2][128 * LDW];

    const int warp = tid >> 5, lane = tid & 31;
    const int wm = warp & 3, wn = warp >> 2;
    const int group = lane >> 2, tig = lane & 3;

    const bool isG0 = (bid < 128);
    int m0, lda, ldb, Klen;
    long long bz = 0;
    const float* A;
    const float* Bm;
    float* C;
    if (isG0) {
        m0 = (bid & 3) * 128;
        bz = bid >> 2;
        A = Amat + bz * (long long)Nn * Ee;     lda = Ee;
        Bm = edge_in + bz * (long long)Ee * Dd; ldb = Dd;
        Klen = Ee;
        C = G0 + bz * (long long)Nn * 128;
    } else {
        const int t = bid - 148;                // 0..511
        m0 = t * 128;                           // rows of flat [Bb*Ee, 128]
        A = edge_in;                            lda = 128;
        Bm = W3v;                               ldb = 128;
        Klen = 128;
        C = out_edge;
    }

    const int ar = tid >> 2, ak2 = (tid & 3) * 4;
    const int tk2 = tid & 15, tnb = (tid >> 4) * 4;

    const uint32_t aBase = smem_u32(&As[0][0]);
    const uint32_t bBase = smem_u32(&Bs[0][0]);
    const uint32_t BUFB  = 128 * LDW * 4;
    const int rowA = wm * 32 + (lane & 7) + ((lane >> 3) & 1) * 8;
    const uint32_t addrA0 = aBase + (uint32_t)((rowA * LDW + ((lane >> 4) & 1) * 4) * 4);
    const int rowB = wn * 32 + (lane & 7) + ((lane >> 4) & 1) * 8;
    const uint32_t addrB0 = bBase + (uint32_t)((rowB * LDW + ((lane >> 3) & 1) * 4) * 4);

    float acc[2][4][4];
#pragma unroll
    for (int i = 0; i < 2; i++)
#pragma unroll
        for (int j = 0; j < 4; j++)
#pragma unroll
            for (int q = 0; q < 4; q++) acc[i][j][q] = 0.f;

    float rsum = 0.f;
    float4 a0, a1, b0, b1;

    auto loadRegs = [&](int it) {
        const int k0 = it * 32;
        const float* asrc = A + (size_t)(m0 + ar) * lda + k0 + ak2 * 2;
        a0 = *(const float4*)asrc;
        a1 = *(const float4*)(asrc + 4);
        if (isG0)
            rsum += ((a0.x + a0.y) + (a0.z + a0.w)) + ((a1.x + a1.y) + (a1.z + a1.w));
        const float* bsrc = Bm + (size_t)(k0 + 2 * tk2) * ldb + tnb;
        b0 = *(const float4*)bsrc;
        b1 = *(const float4*)(bsrc + ldb);
    };

    auto stage = [&](int buf) {
        uint4 aw = { packh2(a0.x, a0.y), packh2(a0.z, a0.w),
                     packh2(a1.x, a1.y), packh2(a1.z, a1.w) };
        *(uint4*)&As[buf][ar * LDW + ak2] = aw;
        Bs[buf][(tnb + 0) * LDW + tk2] = packh2(b0.x, b1.x);
        Bs[buf][(tnb + 1) * LDW + tk2] = packh2(b0.y, b1.y);
        Bs[buf][(tnb + 2) * LDW + tk2] = packh2(b0.z, b1.z);
        Bs[buf][(tnb + 3) * LDW + tk2] = packh2(b0.w, b1.w);
    };

    const int niter = Klen / 32;
    loadRegs(0);
    stage(0);
    __syncthreads();

    for (int it = 0; it < niter; it++) {
        const int buf = it & 1;
        if (it + 1 < niter) loadRegs(it + 1);

#pragma unroll
        for (int s = 0; s < 2; s++) {
            uint32_t af[2][4], bf[4][2];
            const uint32_t aAddr = addrA0 + buf * BUFB + s * 32;
            const uint32_t bAddr = addrB0 + buf * BUFB + s * 32;
            LDSM4(af[0][0], af[0][1], af[0][2], af[0][3], aAddr);
            LDSM4(af[1][0], af[1][1], af[1][2], af[1][3], aAddr + 16 * LDW * 4);
            LDSM4(bf[0][0], bf[0][1], bf[1][0], bf[1][1], bAddr);
            LDSM4(bf[2][0], bf[2][1], bf[3][0], bf[3][1], bAddr + 16 * LDW * 4);
#pragma unroll
            for (int mi = 0; mi < 2; mi++)
#pragma unroll
                for (int ni = 0; ni < 4; ni++)
                    mma_f16(acc[mi][ni], af[mi], bf[ni]);
        }

        if (it + 1 < niter) stage((it + 1) & 1);
        __syncthreads();
    }

    if (isG0) {
        float s = rsum;
        s += __shfl_xor_sync(0xffffffffu, s, 1);
        s += __shfl_xor_sync(0xffffffffu, s, 2);
        if ((tid & 3) == 0)
            rAout[bz * Nn + m0 + ar] = s;
    }

#pragma unroll
    for (int mi = 0; mi < 2; mi++) {
#pragma unroll
        for (int ni = 0; ni < 4; ni++) {
            const int cl = wn * 32 + ni * 8 + 2 * tig;
#pragma unroll
            for (int rr = 0; rr < 2; rr++) {
                const long long r = m0 + wm * 32 + mi * 16 + group + rr * 8;
#pragma unroll
                for (int cc = 0; cc < 2; cc++) {
                    const int col = cl + cc;
                    const float v = acc[mi][ni][rr * 2 + cc];
                    C[r * 128 + col] = isG0 ? v : (v + cvec[256 + col]);
                }
            }
        }
    }
}

// ---------------- prep kernels ------------------------------------------------
__global__ void k_mm128(const float* __restrict__ A, const float* __restrict__ B,
                        float* __restrict__ C) {
    const int r = blockIdx.x, c = threadIdx.x;
    __shared__ float sA[128];
    sA[c] = A[r * 128 + c];
    __syncthreads();
    float s0 = 0.f, s1 = 0.f, s2 = 0.f, s3 = 0.f;
#pragma unroll
    for (int k = 0; k < 128; k += 4) {
        s0 = fmaf(sA[k + 0], B[(k + 0) * 128 + c], s0);
        s1 = fmaf(sA[k + 1], B[(k + 1) * 128 + c], s1);
        s2 = fmaf(sA[k + 2], B[(k + 2) * 128 + c], s2);
        s3 = fmaf(sA[k + 3], B[(k + 3) * 128 + c], s3);
    }
    C[r * 128 + c] = (s0 + s1) + (s2 + s3);
}

__global__ void k_cvec(const float* __restrict__ b, const float* __restrict__ W,
                       const float* __restrict__ W2, float* __restrict__ c) {
    const int col  = blockIdx.x * 8 + (threadIdx.x >> 5);
    const int lane = threadIdx.x & 31;
    float sw = 0.f, sw2 = 0.f;
#pragma unroll
    for (int k = lane; k < 128; k += 32) {
        const float bk = b[k];
        sw  = fmaf(bk, W [k * 128 + col], sw);
        sw2 = fmaf(bk, W2[k * 128 + col], sw2);
    }
#pragma unroll
    for (int o = 16; o; o >>= 1) {
        sw  += __shfl_xor_sync(0xffffffffu, sw, o);
        sw2 += __shfl_xor_sync(0xffffffffu, sw2, o);
    }
    if (lane == 0) {
        const float bc = b[col];
        c[col]       = bc;
        c[128 + col] = bc + sw;
        c[256 + col] = bc + sw + sw2;
    }
}

// ---------------- misc kernels -------------------------------------------------
__global__ void k_final(const float* __restrict__ att, const float* __restrict__ outn,
                        const float* __restrict__ part,
                        float* __restrict__ d_res, float* __restrict__ d_mul) {
    const int b = blockIdx.x, d = threadIdx.x;
    __shared__ float sa[Nn];
    __shared__ float red[128];
    float lm = -1e30f;
#pragma unroll
    for (int i = 0; i < 4; i++) {
        const float v = att[b * Nn + d + i * 128];
        sa[d + i * 128] = v;
        lm = fmaxf(lm, v);
    }
    red[d] = lm;
    __syncthreads();
    for (int s = 64; s; s >>= 1) { if (d < s) red[d] = fmaxf(red[d], red[d + s]); __syncthreads(); }
    const float M = red[0];
    __syncthreads();
    float ls = 0.f;
#pragma unroll
    for (int i = 0; i < 4; i++) {
        const float e = __expf(sa[d + i * 128] - M);
        sa[d + i * 128] = e;
        ls += e;
    }
    red[d] = ls;
    __syncthreads();
    for (int s = 64; s; s >>= 1) { if (d < s) red[d] += red[d + s]; __syncthreads(); }
    const float S = red[0];
    __syncthreads();

    const float* ob = outn + (long long)b * Nn * Dd;
    float acc = 0.f;
#pragma unroll 8
    for (int n = 0; n < Nn; n++) acc = fmaf(sa[n], ob[n * Dd + d], acc);
    acc /= S;
    float resid = 0.f;
#pragma unroll
    for (int c = 0; c < 20; c++) resid += part[(b * 20 + c) * Dd + d];
    resid *= (1.f / 2560.f);
    d_mul[b * Dd + d] = acc;
    d_res[b * Dd + d] = fmaxf(tanhf(acc) + resid, 0.f);
}

// ---------------- host launch ----------------------------------------------------
static float* sym(const void* s) { void* p = nullptr; cudaGetSymbolAddress(&p, s); return (float*)p; }

extern "C" void kernel_launch(void* const* d_in, const int* in_sizes, int n_in,
                              void* d_out, int out_size) {
    const float* prop_in = (const float*)d_in[0];
    const float* edge_in = (const float*)d_in[1];
    const float* Amat    = (const float*)d_in[2];
    const float* link_W  = (const float*)d_in[4];
    const float* link_b  = (const float*)d_in[5];
    const float* reset_W = (const float*)d_in[6];
    const float* reset_b = (const float*)d_in[7];
    const float* upd_W   = (const float*)d_in[8];
    const float* upd_b   = (const float*)d_in[9];
    const float* trans_W = (const float*)d_in[10];
    const float* trans_b = (const float*)d_in[11];
    const float* att_W1  = (const float*)d_in[12];
    const float* att_b1  = (const float*)d_in[13];
    const float* att_W2  = (const float*)d_in[14];
    const float* att_b2  = (const float*)d_in[15];
    const float* out_W   = (const float*)d_in[16];
    const float* out_b   = (const float*)d_in[17];

    float* out      = (float*)d_out;
    float* out_res  = out;
    float* out_mul  = out + Bb * Dd;
    float* out_edge = out + 2 * Bb * Dd;

    float* G0 = sym(g_G0); float* prop = sym(g_prop); float* rp = sym(g_rp);
    float* zbuf = sym(g_zbuf); float* outn = sym(g_outn); float* rA = sym(g_rA);
    float* WrzTs = sym(g_WrzTs); float* TTs = sym(g_TTs);
    float* betarz = sym(g_betarz); float* betah = sym(g_betah); float* brz = sym(g_brz);
    float* attW1T = sym(g_attW1T); float* outWT = sym(g_outWT);
    float* W2 = sym(g_W2); float* W3 = sym(g_W3); float* W3T = sym(g_W3T);
    float* cvec = sym(g_c);
    float* att = sym(g_att); float* part = sym(g_part);

    // --- tiny serial prep ---
    k_mm128<<<128, 128>>>(link_W, link_W, W2);
    k_mm128<<<128, 128>>>(W2, link_W, W3);
    k_cvec<<<16, 256>>>(link_b, link_W, W2, cvec);

    // --- MEGA: G0 GEMM + residual riders + e3 GEMM + fold, one launch ---
    k_mega<<<1684, 512>>>(Amat, edge_in, prop_in, W3, cvec,
                          link_W, W2, reset_W, upd_W, reset_b, upd_b,
                          trans_W, att_W1, out_W,
                          WrzTs, TTs, W3T, attW1T, outWT,
                          betarz, betah, brz,
                          G0, rA, part, out_edge);

    // --- 3 GRU steps ---
    const float* prop_cur = prop_in;
    for (int s = 0; s < NSTEP; s++) {
        gemm_h<3, true, false><<<dim3(2, MROWS / 128, 1), 512>>>(
            G0, prop_cur, 128, 0, WrzTs + (size_t)s * 65536, 256, 0,
            betarz + s * 256, brz,
            zbuf, 0, rp, nullptr, prop_cur, rA, nullptr, 256);
        gemm_h<4, true, false><<<dim3(1, MROWS / 128, 1), 512>>>(
            G0, rp, 128, 0, TTs + (size_t)s * 32768, 256, 0,
            betah + s * 128, trans_b,
            prop, 0, nullptr, zbuf, prop_cur, rA, nullptr, 256);
        prop_cur = prop;
    }

    // --- merged epilogue GEMM: by<128 att score, by>=128 outn ---
    gemm_h<7, false, false><<<dim3(1, 256, 1), 512>>>(
        prop, nullptr, 128, 0, attW1T, 128, 0, att_b1, att_b2,
        att, 0, outn, att_W2, outWT, out_b, nullptr, 128);

    k_final<<<Bb, Dd>>>(att, outn, part, out_res, out_mul);
}